// round 13
// baseline (speedup 1.0000x reference)
#include <cuda_runtime.h>
#include <cuda_fp16.h>
#include <math.h>
#include <cstdint>

#define BATCH 2
#define C0 192
#define HH 192
#define WW 192
#define HW (HH*WW)          // 36864
#define C3 (3*C0)           // 576
#define NH 4
#define HD 48
#define KDIM 192

typedef __half fp16;

// ---------------- scratch (device globals; no allocs allowed) --------------
__device__ fp16  g_qkv1[BATCH*C3*HW];      // after 1x1 conv (fp16)
__device__ float g_normsq[BATCH*2*C0];     // [b][q|k][c]  sum of squares
__device__ float g_attn[BATCH*NH*HD*HD];   // raw dots -> softmaxed attn
__device__ fp16  g_x16[BATCH*C0*HW];       // x fp16
__device__ fp16  g_v16[BATCH*C0*HW];       // v fp16
__device__ fp16  g_k16[BATCH*C0*HW];       // k fp16
__device__ fp16  g_q16[BATCH*C0*HW];       // q fp16
__device__ fp16  g_wq16[C3*C0];            // w_qkv fp16
__device__ fp16  g_w216[BATCH*C0*C0];      // w2 fp16

// ======================= small helpers =====================================
__device__ __forceinline__ uint32_t smem_u32(const void* p) {
    uint32_t a;
    asm("{ .reg .u64 t; cvta.to.shared.u64 t, %1; cvt.u32.u64 %0, t; }"
        : "=r"(a) : "l"(p));
    return a;
}
__device__ __forceinline__ void ldsm4(uint32_t addr, uint32_t* r) {
    asm volatile("ldmatrix.sync.aligned.m8n8.x4.shared.b16 {%0,%1,%2,%3}, [%4];"
        : "=r"(r[0]), "=r"(r[1]), "=r"(r[2]), "=r"(r[3]) : "r"(addr));
}
__device__ __forceinline__ void ldsm4t(uint32_t addr, uint32_t* r) {
    asm volatile("ldmatrix.sync.aligned.m8n8.x4.trans.shared.b16 {%0,%1,%2,%3}, [%4];"
        : "=r"(r[0]), "=r"(r[1]), "=r"(r[2]), "=r"(r[3]) : "r"(addr));
}
__device__ __forceinline__ void mma16816(float* d, const uint32_t* a, const uint32_t* b) {
    asm volatile(
        "mma.sync.aligned.m16n8k16.row.col.f32.f16.f16.f32 "
        "{%0,%1,%2,%3}, {%4,%5,%6,%7}, {%8,%9}, {%0,%1,%2,%3};"
        : "+f"(d[0]), "+f"(d[1]), "+f"(d[2]), "+f"(d[3])
        : "r"(a[0]), "r"(a[1]), "r"(a[2]), "r"(a[3]), "r"(b[0]), "r"(b[1]));
}
__device__ __forceinline__ void cpa16(uint32_t dst, const void* src, int bytes) {
    asm volatile("cp.async.cg.shared.global [%0], [%1], 16, %2;"
        :: "r"(dst), "l"(src), "r"(bytes));
}
#define CP_COMMIT() asm volatile("cp.async.commit_group;")
#define CP_WAIT(n)  asm volatile("cp.async.wait_group %0;" :: "n"(n))

__device__ __forceinline__ uint32_t pack2h(float a, float b) {
    __half2 p = __halves2half2(__float2half_rn(a), __float2half_rn(b));
    return *reinterpret_cast<uint32_t*>(&p);
}

// ======================= conversion kernel =================================
__global__ void __launch_bounds__(256) cvt_f16(
    const float* __restrict__ src, fp16* __restrict__ dst, int total)
{
    int i8 = (blockIdx.x * 256 + threadIdx.x) * 8;
    if (i8 >= total) return;
    float4 v0 = *reinterpret_cast<const float4*>(src + i8);
    float4 v1 = *reinterpret_cast<const float4*>(src + i8 + 4);
    uint4 o;
    o.x = pack2h(v0.x, v0.y); o.y = pack2h(v0.z, v0.w);
    o.z = pack2h(v1.x, v1.y); o.w = pack2h(v1.z, v1.w);
    *reinterpret_cast<uint4*>(dst + i8) = o;
}

// ======================= tensor-core GEMM (1-pass fp16) ====================
// BK=32, 4-stage cp.async pipeline, 4m x 2n warp layout.
#define BM 128
#define BN 128
#define BK 32
#define NCHUNK (KDIM/BK)     // 6
#define SA 40
#define SB 136
#define A_PLANE_B (BM*SA*2)                  // 10240
#define B_PLANE_B (BK*SB*2)                  // 8704
#define OFF_A 0
#define OFF_B (A_PLANE_B)
#define BUF_B (A_PLANE_B + B_PLANE_B)        // 18944
#define NSTAGE 4
#define SMEM_B (NSTAGE*BUF_B)                // 75776

template<bool HALF_OUT>
__global__ void __launch_bounds__(256) gemm_mma(
    const fp16* __restrict__ A, const fp16* __restrict__ B,
    void* __restrict__ Cv, int Mreal, int ldc,
    size_t sAb, size_t sBb, size_t sCb)
{
    extern __shared__ char smem[];
    const uint32_t sb = smem_u32(smem);
    const int tid  = threadIdx.x;
    const int wid  = tid >> 5;
    const int lane = tid & 31;
    const int warp_m = wid & 3;      // 4 m-groups of 32 rows
    const int warp_n = wid >> 2;     // 2 n-groups of 64 cols

    const int bz = blockIdx.z;
    const fp16* Ab = A + bz * sAb;
    const fp16* Bb = B + bz * sBb;

    const int m0 = blockIdx.y * BM;
    const int n0 = blockIdx.x * BN;
    const bool mactive = (m0 + warp_m * 32) < Mreal;

    float acc[2][8][4];
#pragma unroll
    for (int i = 0; i < 2; i++)
#pragma unroll
        for (int j = 0; j < 8; j++)
#pragma unroll
            for (int q = 0; q < 4; q++) acc[i][j][q] = 0.f;

    auto issue = [&](int kc, int buf) {
        uint32_t base = sb + buf * BUF_B;
        // A: 128 rows x 4 segs = 512 chunks, 2/thread
#pragma unroll
        for (int r = 0; r < 2; r++) {
            int c = tid * 2 + r;
            int row = c >> 2, seg = c & 3;
            int grow = m0 + row;
            int ok = (grow < Mreal) ? 16 : 0;
            int gr = (grow < Mreal) ? grow : 0;
            size_t go = (size_t)gr * KDIM + kc + seg * 8;
            uint32_t so = (uint32_t)(row * SA + seg * 8) * 2;
            cpa16(base + OFF_A + so, Ab + go, ok);
        }
        // B: 32 rows x 16 segs = 512 chunks, 2/thread
#pragma unroll
        for (int r = 0; r < 2; r++) {
            int c = tid * 2 + r;
            int row = c >> 4, seg = c & 15;
            size_t go = (size_t)(kc + row) * HW + n0 + seg * 8;
            uint32_t so = (uint32_t)(row * SB + seg * 8) * 2;
            cpa16(base + OFF_B + so, Bb + go, 16);
        }
        CP_COMMIT();
    };

    issue(0, 0);
    issue(BK, 1);
    issue(2 * BK, 2);

    const int arow = warp_m * 32 + (lane & 15);
    const int acolb = (lane >> 4) * 8;
    const int brow = (lane & 7) + ((lane >> 3) & 1) * 8;
    const int bcolb = warp_n * 64 + ((lane >> 4) & 1) * 8;

    for (int ch = 0; ch < NCHUNK; ch++) {
        if (ch < NCHUNK - 2)      { CP_WAIT(2); }
        else if (ch == NCHUNK - 2){ CP_WAIT(1); }
        else                      { CP_WAIT(0); }
        __syncthreads();
        if (ch + 3 < NCHUNK) issue((ch + 3) * BK, (ch + 3) & 3);

        if (mactive) {
            uint32_t base = sb + (ch & 3) * BUF_B;
#pragma unroll
            for (int ks = 0; ks < 2; ks++) {
                uint32_t af[2][4], bf[4][4];
                int acol = ks * 16 + acolb;
#pragma unroll
                for (int mt = 0; mt < 2; mt++) {
                    uint32_t ao = (uint32_t)((arow + mt * 16) * SA + acol) * 2;
                    ldsm4(base + OFF_A + ao, af[mt]);
                }
                int krow = ks * 16 + brow;
#pragma unroll
                for (int p = 0; p < 4; p++) {
                    uint32_t bo = (uint32_t)(krow * SB + bcolb + p * 16) * 2;
                    ldsm4t(base + OFF_B + bo, bf[p]);
                }
#pragma unroll
                for (int mt = 0; mt < 2; mt++)
#pragma unroll
                    for (int nt = 0; nt < 8; nt++)
                        mma16816(acc[mt][nt], af[mt], &bf[nt >> 1][(nt & 1) * 2]);
            }
        }
    }

    const int erow = lane >> 2;
    const int ecol = (lane & 3) * 2;
    if (mactive) {
#pragma unroll
        for (int mt = 0; mt < 2; mt++) {
            int r0 = m0 + warp_m * 32 + mt * 16 + erow;
            int r1 = r0 + 8;
#pragma unroll
            for (int nt = 0; nt < 8; nt++) {
                int cc = n0 + warp_n * 64 + nt * 8 + ecol;
                if (HALF_OUT) {
                    fp16* Cb = (fp16*)Cv + bz * sCb;
                    if (r0 < Mreal)
                        *reinterpret_cast<uint32_t*>(Cb + (size_t)r0 * ldc + cc) =
                            pack2h(acc[mt][nt][0], acc[mt][nt][1]);
                    if (r1 < Mreal)
                        *reinterpret_cast<uint32_t*>(Cb + (size_t)r1 * ldc + cc) =
                            pack2h(acc[mt][nt][2], acc[mt][nt][3]);
                } else {
                    float* Cb = (float*)Cv + bz * sCb;
                    if (r0 < Mreal)
                        *reinterpret_cast<float2*>(Cb + (size_t)r0 * ldc + cc) =
                            make_float2(acc[mt][nt][0], acc[mt][nt][1]);
                    if (r1 < Mreal)
                        *reinterpret_cast<float2*>(Cb + (size_t)r1 * ldc + cc) =
                            make_float2(acc[mt][nt][2], acc[mt][nt][3]);
                }
            }
        }
    }
}

// ============ fused depthwise 3x3 (fp16 in) + q/k/v fp16 + normsq ==========
#define DW_TX 24
#define DW_TY 16
__global__ void __launch_bounds__(DW_TX*DW_TY) dwconv_fused(
    const fp16* __restrict__ in, const float* __restrict__ wdw,
    fp16* __restrict__ q16, fp16* __restrict__ k16, fp16* __restrict__ v16,
    float* __restrict__ normsq)
{
    const int bc = blockIdx.y;           // b*C3 + o
    const int b  = bc / C3;
    const int o  = bc % C3;
    const fp16* ip = in + (size_t)bc * HW;

    float w[9];
#pragma unroll
    for (int i = 0; i < 9; i++) w[i] = __ldg(wdw + o * 9 + i);

    const int y  = blockIdx.x * DW_TY + threadIdx.y;
    const int x0 = threadIdx.x * 8;

    float a[8];
#pragma unroll
    for (int i = 0; i < 8; i++) a[i] = 0.f;

#pragma unroll
    for (int dy = 0; dy < 3; dy++) {
        int yy = y + dy - 1;
        if (yy < 0 || yy >= HH) continue;
        const fp16* rp = ip + (size_t)yy * WW;
        uint4 raw = *reinterpret_cast<const uint4*>(rp + x0);
        const __half2* hh = reinterpret_cast<const __half2*>(&raw);
        float c[8];
#pragma unroll
        for (int j = 0; j < 4; j++) {
            float2 f = __half22float2(hh[j]);
            c[2*j] = f.x; c[2*j+1] = f.y;
        }
        float lft = (x0 > 0)       ? __half2float(rp[x0 - 1]) : 0.f;
        float rgt = (x0 + 8 < WW)  ? __half2float(rp[x0 + 8]) : 0.f;
        float w0 = w[dy*3], w1 = w[dy*3+1], w2 = w[dy*3+2];
        a[0] += w0*lft  + w1*c[0] + w2*c[1];
        a[1] += w0*c[0] + w1*c[1] + w2*c[2];
        a[2] += w0*c[1] + w1*c[2] + w2*c[3];
        a[3] += w0*c[2] + w1*c[3] + w2*c[4];
        a[4] += w0*c[3] + w1*c[4] + w2*c[5];
        a[5] += w0*c[4] + w1*c[5] + w2*c[6];
        a[6] += w0*c[5] + w1*c[6] + w2*c[7];
        a[7] += w0*c[6] + w1*c[7] + w2*rgt;
    }

    const int t = o / C0;                // 0=q, 1=k, 2=v
    const int c = o % C0;
    size_t off = ((size_t)b * C0 + c) * HW + (size_t)y * WW + x0;

    uint4 hv;
    hv.x = pack2h(a[0], a[1]); hv.y = pack2h(a[2], a[3]);
    hv.z = pack2h(a[4], a[5]); hv.w = pack2h(a[6], a[7]);

    fp16* dst = (t == 0) ? q16 : (t == 1) ? k16 : v16;
    *reinterpret_cast<uint4*>(dst + off) = hv;

    if (t < 2) {
        float s = 0.f;
#pragma unroll
        for (int i = 0; i < 8; i++) s += a[i] * a[i];
#pragma unroll
        for (int offm = 16; offm > 0; offm >>= 1)
            s += __shfl_xor_sync(0xffffffffu, s, offm);
        int lane = (threadIdx.y * DW_TX + threadIdx.x) & 31;
        if (lane == 0)
            atomicAdd(&normsq[(b * 2 + t) * C0 + c], s);
    }
}

// ---------------- zero attn + normsq ---------------------------------------
__global__ void zero_small(float* __restrict__ attn, float* __restrict__ normsq)
{
    int i = blockIdx.x * 256 + threadIdx.x;
    if (i < BATCH * NH * HD * HD) attn[i] = 0.f;
    if (i < BATCH * 2 * C0) normsq[i] = 0.f;
}

// ---------------- tensor-core q·k^T (1-pass fp16) --------------------------
#define AT_NSPL 18
#define AT_KBLK (HW/AT_NSPL)   // 2048
#define AT_SK 128
#define AT_SUB (AT_KBLK/AT_SK) // 16
#define AT_SROW 136
#define AT_PLANE (48*AT_SROW*2)    // 13056
#define AT_STAGE (2*AT_PLANE)      // 26112
#define AT_SMEM (2*AT_STAGE)       // 52224

__global__ void __launch_bounds__(256) attn_mma(
    const fp16* __restrict__ q16, const fp16* __restrict__ k16,
    float* __restrict__ attn)
{
    extern __shared__ char smem[];
    const uint32_t sb = smem_u32(smem);
    const int tid  = threadIdx.x;
    const int wid  = tid >> 5;
    const int lane = tid & 31;

    const int bh = blockIdx.y;
    const int b = bh / NH, h = bh % NH;
    const size_t rowbase = ((size_t)b * C0 + h * HD) * HW;
    const fp16* pl[2] = { q16 + rowbase, k16 + rowbase };
    const size_t kblk0 = (size_t)blockIdx.x * AT_KBLK;

    float acc[3][6][4];
#pragma unroll
    for (int i = 0; i < 3; i++)
#pragma unroll
        for (int j = 0; j < 6; j++)
#pragma unroll
            for (int q = 0; q < 4; q++) acc[i][j][q] = 0.f;

    auto fill = [&](int sub, int stg) {
        uint32_t base = sb + stg * AT_STAGE;
        size_t k0 = kblk0 + (size_t)sub * AT_SK;
#pragma unroll
        for (int p = 0; p < 2; p++) {
#pragma unroll
            for (int r = 0; r < 3; r++) {
                int cc = tid + r * 256;
                int row = cc >> 4, seg = cc & 15;
                cpa16(base + p * AT_PLANE + (uint32_t)(row * AT_SROW + seg * 8) * 2,
                      pl[p] + (size_t)row * HW + k0 + seg * 8, 16);
            }
        }
        CP_COMMIT();
    };

    fill(0, 0);

    const int kofs = wid * 16;
    const int a_r = lane & 15;
    const int a_c = kofs + (lane >> 4) * 8;
    const int b_r = (lane & 7) + ((lane >> 4) & 1) * 8;
    const int b_c = kofs + ((lane >> 3) & 1) * 8;

    for (int sub = 0; sub < AT_SUB; sub++) {
        CP_WAIT(0);
        __syncthreads();
        if (sub < AT_SUB - 1) fill(sub + 1, (sub + 1) & 1);

        uint32_t base = sb + (sub & 1) * AT_STAGE;
        uint32_t qf[3][4], kf[3][4];
#pragma unroll
        for (int mt = 0; mt < 3; mt++) {
            uint32_t ao = (uint32_t)((mt * 16 + a_r) * AT_SROW + a_c) * 2;
            ldsm4(base + 0 * AT_PLANE + ao, qf[mt]);
        }
#pragma unroll
        for (int nt2 = 0; nt2 < 3; nt2++) {
            uint32_t bo = (uint32_t)((nt2 * 16 + b_r) * AT_SROW + b_c) * 2;
            ldsm4(base + 1 * AT_PLANE + bo, kf[nt2]);
        }
#pragma unroll
        for (int mt = 0; mt < 3; mt++)
#pragma unroll
            for (int nt = 0; nt < 6; nt++)
                mma16816(acc[mt][nt], qf[mt], &kf[nt >> 1][(nt & 1) * 2]);
        __syncthreads();
    }

    float* red = reinterpret_cast<float*>(smem);   // [48][49]
    for (int i = tid; i < 48 * 49; i += 256) red[i] = 0.f;
    __syncthreads();
    const int erow = lane >> 2;
    const int ecol = (lane & 3) * 2;
#pragma unroll
    for (int mt = 0; mt < 3; mt++) {
        int r0 = mt * 16 + erow;
#pragma unroll
        for (int nt = 0; nt < 6; nt++) {
            int cc = nt * 8 + ecol;
            atomicAdd(&red[r0 * 49 + cc],       acc[mt][nt][0]);
            atomicAdd(&red[r0 * 49 + cc + 1],   acc[mt][nt][1]);
            atomicAdd(&red[(r0 + 8) * 49 + cc],     acc[mt][nt][2]);
            atomicAdd(&red[(r0 + 8) * 49 + cc + 1], acc[mt][nt][3]);
        }
    }
    __syncthreads();
    float* ap = attn + (size_t)bh * HD * HD;
    for (int i = tid; i < HD * HD; i += 256) {
        int r = i / HD, cl = i % HD;
        atomicAdd(&ap[i], red[r * 49 + cl]);
    }
}

// ---------------- scale by norms + temperature, softmax over e -------------
__global__ void softmax_attn(float* __restrict__ attn, const float* __restrict__ normsq,
                             const float* __restrict__ logtemp)
{
    const int bh = blockIdx.x;
    const int b = bh / NH, h = bh % NH;
    const int d = threadIdx.x;
    if (d >= HD) return;

    float lt = logtemp[h];
    float temp = (lt > 20.f ? lt : log1pf(expf(lt))) + 1e-6f;

    const float* nq = normsq + (b * 2 + 0) * C0 + h * HD;
    const float* nk = normsq + (b * 2 + 1) * C0 + h * HD;
    float* row = attn + ((size_t)bh * HD + d) * HD;
    const float qn = fmaxf(sqrtf(nq[d]), 1e-12f);

    float vals[HD];
    float mx = -1e30f;
#pragma unroll
    for (int e = 0; e < HD; e++) {
        float kn = fmaxf(sqrtf(nk[e]), 1e-12f);
        float v = row[e] / (qn * kn) * temp;
        vals[e] = v;
        mx = fmaxf(mx, v);
    }
    float s = 0.f;
#pragma unroll
    for (int e = 0; e < HD; e++) {
        vals[e] = expf(vals[e] - mx);
        s += vals[e];
    }
    float inv = 1.f / s;
#pragma unroll
    for (int e = 0; e < HD; e++) row[e] = vals[e] * inv;
}

// ---------------- W2[b] = w_proj @ blockdiag(attn[b]) -> fp16 --------------
__global__ void build_w2(const float* __restrict__ wproj, const float* __restrict__ attn,
                         fp16* __restrict__ w2)
{
    int idx = blockIdx.x * 256 + threadIdx.x;
    if (idx >= BATCH * C0 * C0) return;
    int cc = idx % C0;
    int o  = (idx / C0) % C0;
    int b  = idx / (C0 * C0);
    int h = cc / HD, e = cc % HD;
    float s = 0.f;
#pragma unroll
    for (int d = 0; d < HD; d++)
        s += wproj[o * C0 + h * HD + d] * attn[(((size_t)b * NH + h) * HD + d) * HD + e];
    w2[idx] = __float2half_rn(s);
}

// ---------------- launcher -------------------------------------------------
extern "C" void kernel_launch(void* const* d_in, const int* in_sizes, int n_in,
                              void* d_out, int out_size)
{
    const float* x      = (const float*)d_in[0];
    const float* w_qkv  = (const float*)d_in[1];
    const float* w_dw   = (const float*)d_in[2];
    const float* w_proj = (const float*)d_in[3];
    const float* ltemp  = (const float*)d_in[4];
    float* out = (float*)d_out;

    float *normsq, *attn;
    fp16 *qkv1, *x16, *v16, *k16, *q16, *wq16, *w216;
    cudaGetSymbolAddress((void**)&qkv1, g_qkv1);
    cudaGetSymbolAddress((void**)&normsq, g_normsq);
    cudaGetSymbolAddress((void**)&attn, g_attn);
    cudaGetSymbolAddress((void**)&x16, g_x16);
    cudaGetSymbolAddress((void**)&v16, g_v16);
    cudaGetSymbolAddress((void**)&k16, g_k16);
    cudaGetSymbolAddress((void**)&q16, g_q16);
    cudaGetSymbolAddress((void**)&wq16, g_wq16);
    cudaGetSymbolAddress((void**)&w216, g_w216);

    cudaFuncSetAttribute(gemm_mma<true>,  cudaFuncAttributeMaxDynamicSharedMemorySize, SMEM_B);
    cudaFuncSetAttribute(gemm_mma<false>, cudaFuncAttributeMaxDynamicSharedMemorySize, SMEM_B);
    cudaFuncSetAttribute(attn_mma, cudaFuncAttributeMaxDynamicSharedMemorySize, AT_SMEM);

    // 0) convert x, w_qkv -> fp16; zero accumulators
    {
        int total = BATCH * C0 * HW;
        cvt_f16<<<total / 8 / 256, 256>>>(x, x16, total);
        int wtot = C3 * C0;
        cvt_f16<<<(wtot / 8 + 255) / 256, 256>>>(w_qkv, wq16, wtot);
        zero_small<<<(BATCH * NH * HD * HD + 255) / 256, 256>>>(attn, normsq);
    }
    // 1) qkv1 = w_qkv @ x  (fp16 out)
    {
        dim3 grid(HW / BN, (C3 + BM - 1) / BM, BATCH);
        gemm_mma<true><<<grid, 256, SMEM_B>>>(wq16, x16, qkv1,
                                              C3, HW, 0, (size_t)C0 * HW,
                                              (size_t)C3 * HW);
    }
    // 2) fused depthwise 3x3 -> q,k,v fp16 + normsq
    {
        dim3 grid(HH / DW_TY, BATCH * C3);
        dwconv_fused<<<grid, dim3(DW_TX, DW_TY)>>>(qkv1, w_dw, q16, k16, v16, normsq);
    }
    // 3) tensor-core q.k^T
    {
        dim3 grid(AT_NSPL, BATCH * NH);
        attn_mma<<<grid, 256, AT_SMEM>>>(q16, k16, attn);
    }
    // 4) softmax
    softmax_attn<<<BATCH * NH, 64>>>(attn, normsq, ltemp);
    // 5) W2 -> fp16
    build_w2<<<(BATCH * C0 * C0 + 255) / 256, 256>>>(w_proj, attn, w216);
    // 6) out = W2 @ v  (fp32 out)
    {
        dim3 grid(HW / BN, (C0 + BM - 1) / BM, BATCH);
        gemm_mma<false><<<grid, 256, SMEM_B>>>(w216, v16, out,
                                               C0, HW, (size_t)C0 * C0,
                                               (size_t)C0 * HW, (size_t)C0 * HW);
    }
}

// round 14
// speedup vs baseline: 1.1876x; 1.1876x over previous
#include <cuda_runtime.h>
#include <cuda_fp16.h>
#include <math.h>
#include <cstdint>

#define BATCH 2
#define C0 192
#define HH 192
#define WW 192
#define HW (HH*WW)          // 36864
#define C3 (3*C0)           // 576
#define NH 4
#define HD 48
#define KDIM 192

typedef __half fp16;

// ---------------- scratch (device globals; no allocs allowed) --------------
__device__ fp16  g_qkv1[BATCH*C3*HW];      // after 1x1 conv (fp16)
__device__ float g_normsq[BATCH*2*C0];     // [b][q|k][c]  sum of squares
__device__ float g_attn[BATCH*NH*HD*HD];   // raw dots -> softmaxed attn
__device__ fp16  g_x16[BATCH*C0*HW];       // x fp16
__device__ fp16  g_v16[BATCH*C0*HW];       // v fp16
__device__ fp16  g_k16[BATCH*C0*HW];       // k fp16
__device__ fp16  g_q16[BATCH*C0*HW];       // q fp16
__device__ fp16  g_wqh[C3*C0];             // w_qkv hi
__device__ fp16  g_wql[C3*C0];             // w_qkv lo
__device__ fp16  g_w2h[BATCH*C0*C0];       // w2 hi
__device__ fp16  g_w2l[BATCH*C0*C0];       // w2 lo

// ======================= small helpers =====================================
__device__ __forceinline__ uint32_t smem_u32(const void* p) {
    uint32_t a;
    asm("{ .reg .u64 t; cvta.to.shared.u64 t, %1; cvt.u32.u64 %0, t; }"
        : "=r"(a) : "l"(p));
    return a;
}
__device__ __forceinline__ void ldsm4(uint32_t addr, uint32_t* r) {
    asm volatile("ldmatrix.sync.aligned.m8n8.x4.shared.b16 {%0,%1,%2,%3}, [%4];"
        : "=r"(r[0]), "=r"(r[1]), "=r"(r[2]), "=r"(r[3]) : "r"(addr));
}
__device__ __forceinline__ void ldsm4t(uint32_t addr, uint32_t* r) {
    asm volatile("ldmatrix.sync.aligned.m8n8.x4.trans.shared.b16 {%0,%1,%2,%3}, [%4];"
        : "=r"(r[0]), "=r"(r[1]), "=r"(r[2]), "=r"(r[3]) : "r"(addr));
}
__device__ __forceinline__ void mma16816(float* d, const uint32_t* a, const uint32_t* b) {
    asm volatile(
        "mma.sync.aligned.m16n8k16.row.col.f32.f16.f16.f32 "
        "{%0,%1,%2,%3}, {%4,%5,%6,%7}, {%8,%9}, {%0,%1,%2,%3};"
        : "+f"(d[0]), "+f"(d[1]), "+f"(d[2]), "+f"(d[3])
        : "r"(a[0]), "r"(a[1]), "r"(a[2]), "r"(a[3]), "r"(b[0]), "r"(b[1]));
}
__device__ __forceinline__ void cpa16(uint32_t dst, const void* src, int bytes) {
    asm volatile("cp.async.cg.shared.global [%0], [%1], 16, %2;"
        :: "r"(dst), "l"(src), "r"(bytes));
}
#define CP_COMMIT() asm volatile("cp.async.commit_group;")
#define CP_WAIT(n)  asm volatile("cp.async.wait_group %0;" :: "n"(n))

__device__ __forceinline__ uint32_t pack2h(float a, float b) {
    __half2 p = __halves2half2(__float2half_rn(a), __float2half_rn(b));
    return *reinterpret_cast<uint32_t*>(&p);
}

// ======================= conversion kernels ================================
__global__ void __launch_bounds__(256) cvt_f16(
    const float* __restrict__ src, fp16* __restrict__ dst, int total)
{
    int i8 = (blockIdx.x * 256 + threadIdx.x) * 8;
    if (i8 >= total) return;
    float4 v0 = *reinterpret_cast<const float4*>(src + i8);
    float4 v1 = *reinterpret_cast<const float4*>(src + i8 + 4);
    uint4 o;
    o.x = pack2h(v0.x, v0.y); o.y = pack2h(v0.z, v0.w);
    o.z = pack2h(v1.x, v1.y); o.w = pack2h(v1.z, v1.w);
    *reinterpret_cast<uint4*>(dst + i8) = o;
}

__global__ void __launch_bounds__(256) split_f16(
    const float* __restrict__ src, fp16* __restrict__ h, fp16* __restrict__ l, int total)
{
    int i4 = (blockIdx.x * 256 + threadIdx.x) * 4;
    if (i4 >= total) return;
    float4 v = *reinterpret_cast<const float4*>(src + i4);
    fp16 h0 = __float2half_rn(v.x), h1 = __float2half_rn(v.y);
    fp16 h2 = __float2half_rn(v.z), h3 = __float2half_rn(v.w);
    float l0 = v.x - __half2float(h0), l1 = v.y - __half2float(h1);
    float l2 = v.z - __half2float(h2), l3 = v.w - __half2float(h3);
    uint2 ho, lo;
    ho.x = pack2h(__half2float(h0), __half2float(h1));
    ho.y = pack2h(__half2float(h2), __half2float(h3));
    lo.x = pack2h(l0, l1); lo.y = pack2h(l2, l3);
    *reinterpret_cast<uint2*>(h + i4) = ho;
    *reinterpret_cast<uint2*>(l + i4) = lo;
}

// ======================= tensor-core GEMM (2-pass fp16 split) ==============
// R10 config: BK=32, 3-stage cp.async, 4m x 2n warps, A hi/lo + B single.
#define BM 128
#define BN 128
#define BK 32
#define NCHUNK (KDIM/BK)     // 6
#define SA 40
#define SB 136
#define A_PLANE_B (BM*SA*2)                  // 10240
#define B_PLANE_B (BK*SB*2)                  // 8704
#define OFF_AH 0
#define OFF_AL (A_PLANE_B)
#define OFF_B  (2*A_PLANE_B)
#define BUF_B  (2*A_PLANE_B + B_PLANE_B)     // 29184
#define NSTAGE 3
#define SMEM_B (NSTAGE*BUF_B)                // 87552

template<bool HALF_OUT>
__global__ void __launch_bounds__(256) gemm_mma(
    const fp16* __restrict__ Ah, const fp16* __restrict__ Al,
    const fp16* __restrict__ B,
    void* __restrict__ Cv, int Mreal, int ldc,
    size_t sAb, size_t sBb, size_t sCb)
{
    extern __shared__ char smem[];
    const uint32_t sb = smem_u32(smem);
    const int tid  = threadIdx.x;
    const int wid  = tid >> 5;
    const int lane = tid & 31;
    const int warp_m = wid & 3;      // 4 m-groups of 32 rows
    const int warp_n = wid >> 2;     // 2 n-groups of 64 cols

    const int bz = blockIdx.z;
    const fp16* Ahb = Ah + bz * sAb;
    const fp16* Alb = Al + bz * sAb;
    const fp16* Bb  = B  + bz * sBb;

    const int m0 = blockIdx.y * BM;
    const int n0 = blockIdx.x * BN;
    const bool mactive = (m0 + warp_m * 32) < Mreal;

    float acc[2][8][4];
#pragma unroll
    for (int i = 0; i < 2; i++)
#pragma unroll
        for (int j = 0; j < 8; j++)
#pragma unroll
            for (int q = 0; q < 4; q++) acc[i][j][q] = 0.f;

    auto issue = [&](int kc, int buf) {
        uint32_t base = sb + buf * BUF_B;
#pragma unroll
        for (int r = 0; r < 2; r++) {
            int c = tid * 2 + r;
            int row = c >> 2, seg = c & 3;
            int grow = m0 + row;
            int ok = (grow < Mreal) ? 16 : 0;
            int gr = (grow < Mreal) ? grow : 0;
            size_t go = (size_t)gr * KDIM + kc + seg * 8;
            uint32_t so = (uint32_t)(row * SA + seg * 8) * 2;
            cpa16(base + OFF_AH + so, Ahb + go, ok);
            cpa16(base + OFF_AL + so, Alb + go, ok);
        }
#pragma unroll
        for (int r = 0; r < 2; r++) {
            int c = tid * 2 + r;
            int row = c >> 4, seg = c & 15;
            size_t go = (size_t)(kc + row) * HW + n0 + seg * 8;
            uint32_t so = (uint32_t)(row * SB + seg * 8) * 2;
            cpa16(base + OFF_B + so, Bb + go, 16);
        }
        CP_COMMIT();
    };

    issue(0, 0);
    issue(BK, 1);

    const int arow = warp_m * 32 + (lane & 15);
    const int acolb = (lane >> 4) * 8;
    const int brow = (lane & 7) + ((lane >> 3) & 1) * 8;
    const int bcolb = warp_n * 64 + ((lane >> 4) & 1) * 8;

    int buf = 0;
    for (int ch = 0; ch < NCHUNK; ch++) {
        if (ch < NCHUNK - 1) { CP_WAIT(1); } else { CP_WAIT(0); }
        __syncthreads();
        if (ch < NCHUNK - 2) {
            int nb = buf + 2; if (nb >= NSTAGE) nb -= NSTAGE;
            issue((ch + 2) * BK, nb);
        }

        if (mactive) {
            uint32_t base = sb + buf * BUF_B;
#pragma unroll
            for (int ks = 0; ks < 2; ks++) {
                uint32_t ah[2][4], al[2][4], bh[4][4];
                int acol = ks * 16 + acolb;
#pragma unroll
                for (int mt = 0; mt < 2; mt++) {
                    uint32_t ao = (uint32_t)((arow + mt * 16) * SA + acol) * 2;
                    ldsm4(base + OFF_AH + ao, ah[mt]);
                    ldsm4(base + OFF_AL + ao, al[mt]);
                }
                int krow = ks * 16 + brow;
#pragma unroll
                for (int p = 0; p < 4; p++) {
                    uint32_t bo = (uint32_t)(krow * SB + bcolb + p * 16) * 2;
                    ldsm4t(base + OFF_B + bo, bh[p]);
                }
#pragma unroll
                for (int mt = 0; mt < 2; mt++)
#pragma unroll
                    for (int nt = 0; nt < 8; nt++) {
                        const uint32_t* bf = &bh[nt >> 1][(nt & 1) * 2];
                        mma16816(acc[mt][nt], ah[mt], bf);
                        mma16816(acc[mt][nt], al[mt], bf);
                    }
            }
        }
        buf++; if (buf >= NSTAGE) buf = 0;
    }

    const int erow = lane >> 2;
    const int ecol = (lane & 3) * 2;
    if (mactive) {
#pragma unroll
        for (int mt = 0; mt < 2; mt++) {
            int r0 = m0 + warp_m * 32 + mt * 16 + erow;
            int r1 = r0 + 8;
#pragma unroll
            for (int nt = 0; nt < 8; nt++) {
                int cc = n0 + warp_n * 64 + nt * 8 + ecol;
                if (HALF_OUT) {
                    fp16* Cb = (fp16*)Cv + bz * sCb;
                    if (r0 < Mreal)
                        *reinterpret_cast<uint32_t*>(Cb + (size_t)r0 * ldc + cc) =
                            pack2h(acc[mt][nt][0], acc[mt][nt][1]);
                    if (r1 < Mreal)
                        *reinterpret_cast<uint32_t*>(Cb + (size_t)r1 * ldc + cc) =
                            pack2h(acc[mt][nt][2], acc[mt][nt][3]);
                } else {
                    float* Cb = (float*)Cv + bz * sCb;
                    if (r0 < Mreal)
                        *reinterpret_cast<float2*>(Cb + (size_t)r0 * ldc + cc) =
                            make_float2(acc[mt][nt][0], acc[mt][nt][1]);
                    if (r1 < Mreal)
                        *reinterpret_cast<float2*>(Cb + (size_t)r1 * ldc + cc) =
                            make_float2(acc[mt][nt][2], acc[mt][nt][3]);
                }
            }
        }
    }
}

// ============ fused depthwise 3x3 (fp16 in) + q/k/v fp16 + normsq ==========
#define DW_TX 24
#define DW_TY 16
__global__ void __launch_bounds__(DW_TX*DW_TY) dwconv_fused(
    const fp16* __restrict__ in, const float* __restrict__ wdw,
    fp16* __restrict__ q16, fp16* __restrict__ k16, fp16* __restrict__ v16,
    float* __restrict__ normsq)
{
    const int bc = blockIdx.y;           // b*C3 + o
    const int b  = bc / C3;
    const int o  = bc % C3;
    const fp16* ip = in + (size_t)bc * HW;

    float w[9];
#pragma unroll
    for (int i = 0; i < 9; i++) w[i] = __ldg(wdw + o * 9 + i);

    const int y  = blockIdx.x * DW_TY + threadIdx.y;
    const int x0 = threadIdx.x * 8;

    float a[8];
#pragma unroll
    for (int i = 0; i < 8; i++) a[i] = 0.f;

#pragma unroll
    for (int dy = 0; dy < 3; dy++) {
        int yy = y + dy - 1;
        if (yy < 0 || yy >= HH) continue;
        const fp16* rp = ip + (size_t)yy * WW;
        uint4 raw = *reinterpret_cast<const uint4*>(rp + x0);
        const __half2* hh = reinterpret_cast<const __half2*>(&raw);
        float c[8];
#pragma unroll
        for (int j = 0; j < 4; j++) {
            float2 f = __half22float2(hh[j]);
            c[2*j] = f.x; c[2*j+1] = f.y;
        }
        float lft = (x0 > 0)       ? __half2float(rp[x0 - 1]) : 0.f;
        float rgt = (x0 + 8 < WW)  ? __half2float(rp[x0 + 8]) : 0.f;
        float w0 = w[dy*3], w1 = w[dy*3+1], w2 = w[dy*3+2];
        a[0] += w0*lft  + w1*c[0] + w2*c[1];
        a[1] += w0*c[0] + w1*c[1] + w2*c[2];
        a[2] += w0*c[1] + w1*c[2] + w2*c[3];
        a[3] += w0*c[2] + w1*c[3] + w2*c[4];
        a[4] += w0*c[3] + w1*c[4] + w2*c[5];
        a[5] += w0*c[4] + w1*c[5] + w2*c[6];
        a[6] += w0*c[5] + w1*c[6] + w2*c[7];
        a[7] += w0*c[6] + w1*c[7] + w2*rgt;
    }

    const int t = o / C0;                // 0=q, 1=k, 2=v
    const int c = o % C0;
    size_t off = ((size_t)b * C0 + c) * HW + (size_t)y * WW + x0;

    uint4 hv;
    hv.x = pack2h(a[0], a[1]); hv.y = pack2h(a[2], a[3]);
    hv.z = pack2h(a[4], a[5]); hv.w = pack2h(a[6], a[7]);

    fp16* dst = (t == 0) ? q16 : (t == 1) ? k16 : v16;
    *reinterpret_cast<uint4*>(dst + off) = hv;

    if (t < 2) {
        float s = 0.f;
#pragma unroll
        for (int i = 0; i < 8; i++) s += a[i] * a[i];
#pragma unroll
        for (int offm = 16; offm > 0; offm >>= 1)
            s += __shfl_xor_sync(0xffffffffu, s, offm);
        int lane = (threadIdx.y * DW_TX + threadIdx.x) & 31;
        if (lane == 0)
            atomicAdd(&normsq[(b * 2 + t) * C0 + c], s);
    }
}

// ---------------- zero attn + normsq ---------------------------------------
__global__ void zero_small(float* __restrict__ attn, float* __restrict__ normsq)
{
    int i = blockIdx.x * 256 + threadIdx.x;
    if (i < BATCH * NH * HD * HD) attn[i] = 0.f;
    if (i < BATCH * 2 * C0) normsq[i] = 0.f;
}

// ---------------- tensor-core q·k^T (1-pass fp16) --------------------------
#define AT_NSPL 18
#define AT_KBLK (HW/AT_NSPL)   // 2048
#define AT_SK 128
#define AT_SUB (AT_KBLK/AT_SK) // 16
#define AT_SROW 136
#define AT_PLANE (48*AT_SROW*2)    // 13056
#define AT_STAGE (2*AT_PLANE)      // 26112
#define AT_SMEM (2*AT_STAGE)       // 52224

__global__ void __launch_bounds__(256) attn_mma(
    const fp16* __restrict__ q16, const fp16* __restrict__ k16,
    float* __restrict__ attn)
{
    extern __shared__ char smem[];
    const uint32_t sb = smem_u32(smem);
    const int tid  = threadIdx.x;
    const int wid  = tid >> 5;
    const int lane = tid & 31;

    const int bh = blockIdx.y;
    const int b = bh / NH, h = bh % NH;
    const size_t rowbase = ((size_t)b * C0 + h * HD) * HW;
    const fp16* pl[2] = { q16 + rowbase, k16 + rowbase };
    const size_t kblk0 = (size_t)blockIdx.x * AT_KBLK;

    float acc[3][6][4];
#pragma unroll
    for (int i = 0; i < 3; i++)
#pragma unroll
        for (int j = 0; j < 6; j++)
#pragma unroll
            for (int q = 0; q < 4; q++) acc[i][j][q] = 0.f;

    auto fill = [&](int sub, int stg) {
        uint32_t base = sb + stg * AT_STAGE;
        size_t k0 = kblk0 + (size_t)sub * AT_SK;
#pragma unroll
        for (int p = 0; p < 2; p++) {
#pragma unroll
            for (int r = 0; r < 3; r++) {
                int cc = tid + r * 256;
                int row = cc >> 4, seg = cc & 15;
                cpa16(base + p * AT_PLANE + (uint32_t)(row * AT_SROW + seg * 8) * 2,
                      pl[p] + (size_t)row * HW + k0 + seg * 8, 16);
            }
        }
        CP_COMMIT();
    };

    fill(0, 0);

    const int kofs = wid * 16;
    const int a_r = lane & 15;
    const int a_c = kofs + (lane >> 4) * 8;
    const int b_r = (lane & 7) + ((lane >> 4) & 1) * 8;
    const int b_c = kofs + ((lane >> 3) & 1) * 8;

    for (int sub = 0; sub < AT_SUB; sub++) {
        CP_WAIT(0);
        __syncthreads();
        if (sub < AT_SUB - 1) fill(sub + 1, (sub + 1) & 1);

        uint32_t base = sb + (sub & 1) * AT_STAGE;
        uint32_t qf[3][4], kf[3][4];
#pragma unroll
        for (int mt = 0; mt < 3; mt++) {
            uint32_t ao = (uint32_t)((mt * 16 + a_r) * AT_SROW + a_c) * 2;
            ldsm4(base + 0 * AT_PLANE + ao, qf[mt]);
        }
#pragma unroll
        for (int nt2 = 0; nt2 < 3; nt2++) {
            uint32_t bo = (uint32_t)((nt2 * 16 + b_r) * AT_SROW + b_c) * 2;
            ldsm4(base + 1 * AT_PLANE + bo, kf[nt2]);
        }
#pragma unroll
        for (int mt = 0; mt < 3; mt++)
#pragma unroll
            for (int nt = 0; nt < 6; nt++)
                mma16816(acc[mt][nt], qf[mt], &kf[nt >> 1][(nt & 1) * 2]);
        __syncthreads();
    }

    float* red = reinterpret_cast<float*>(smem);   // [48][49]
    for (int i = tid; i < 48 * 49; i += 256) red[i] = 0.f;
    __syncthreads();
    const int erow = lane >> 2;
    const int ecol = (lane & 3) * 2;
#pragma unroll
    for (int mt = 0; mt < 3; mt++) {
        int r0 = mt * 16 + erow;
#pragma unroll
        for (int nt = 0; nt < 6; nt++) {
            int cc = nt * 8 + ecol;
            atomicAdd(&red[r0 * 49 + cc],       acc[mt][nt][0]);
            atomicAdd(&red[r0 * 49 + cc + 1],   acc[mt][nt][1]);
            atomicAdd(&red[(r0 + 8) * 49 + cc],     acc[mt][nt][2]);
            atomicAdd(&red[(r0 + 8) * 49 + cc + 1], acc[mt][nt][3]);
        }
    }
    __syncthreads();
    float* ap = attn + (size_t)bh * HD * HD;
    for (int i = tid; i < HD * HD; i += 256) {
        int r = i / HD, cl = i % HD;
        atomicAdd(&ap[i], red[r * 49 + cl]);
    }
}

// ---------------- scale by norms + temperature, softmax over e -------------
__global__ void softmax_attn(float* __restrict__ attn, const float* __restrict__ normsq,
                             const float* __restrict__ logtemp)
{
    const int bh = blockIdx.x;
    const int b = bh / NH, h = bh % NH;
    const int d = threadIdx.x;
    if (d >= HD) return;

    float lt = logtemp[h];
    float temp = (lt > 20.f ? lt : log1pf(expf(lt))) + 1e-6f;

    const float* nq = normsq + (b * 2 + 0) * C0 + h * HD;
    const float* nk = normsq + (b * 2 + 1) * C0 + h * HD;
    float* row = attn + ((size_t)bh * HD + d) * HD;
    const float qn = fmaxf(sqrtf(nq[d]), 1e-12f);

    float vals[HD];
    float mx = -1e30f;
#pragma unroll
    for (int e = 0; e < HD; e++) {
        float kn = fmaxf(sqrtf(nk[e]), 1e-12f);
        float v = row[e] / (qn * kn) * temp;
        vals[e] = v;
        mx = fmaxf(mx, v);
    }
    float s = 0.f;
#pragma unroll
    for (int e = 0; e < HD; e++) {
        vals[e] = expf(vals[e] - mx);
        s += vals[e];
    }
    float inv = 1.f / s;
#pragma unroll
    for (int e = 0; e < HD; e++) row[e] = vals[e] * inv;
}

// ---------------- W2[b] = w_proj @ blockdiag(attn[b]) -> fp16 hi/lo --------
__global__ void build_w2(const float* __restrict__ wproj, const float* __restrict__ attn,
                         fp16* __restrict__ w2h, fp16* __restrict__ w2l)
{
    int idx = blockIdx.x * 256 + threadIdx.x;
    if (idx >= BATCH * C0 * C0) return;
    int cc = idx % C0;
    int o  = (idx / C0) % C0;
    int b  = idx / (C0 * C0);
    int h = cc / HD, e = cc % HD;
    float s = 0.f;
#pragma unroll
    for (int d = 0; d < HD; d++)
        s += wproj[o * C0 + h * HD + d] * attn[(((size_t)b * NH + h) * HD + d) * HD + e];
    fp16 hi = __float2half_rn(s);
    fp16 lo = __float2half_rn(s - __half2float(hi));
    w2h[idx] = hi;
    w2l[idx] = lo;
}

// ---------------- launcher -------------------------------------------------
extern "C" void kernel_launch(void* const* d_in, const int* in_sizes, int n_in,
                              void* d_out, int out_size)
{
    const float* x      = (const float*)d_in[0];
    const float* w_qkv  = (const float*)d_in[1];
    const float* w_dw   = (const float*)d_in[2];
    const float* w_proj = (const float*)d_in[3];
    const float* ltemp  = (const float*)d_in[4];
    float* out = (float*)d_out;

    float *normsq, *attn;
    fp16 *qkv1, *x16, *v16, *k16, *q16, *wqh, *wql, *w2h, *w2l;
    cudaGetSymbolAddress((void**)&qkv1, g_qkv1);
    cudaGetSymbolAddress((void**)&normsq, g_normsq);
    cudaGetSymbolAddress((void**)&attn, g_attn);
    cudaGetSymbolAddress((void**)&x16, g_x16);
    cudaGetSymbolAddress((void**)&v16, g_v16);
    cudaGetSymbolAddress((void**)&k16, g_k16);
    cudaGetSymbolAddress((void**)&q16, g_q16);
    cudaGetSymbolAddress((void**)&wqh, g_wqh);
    cudaGetSymbolAddress((void**)&wql, g_wql);
    cudaGetSymbolAddress((void**)&w2h, g_w2h);
    cudaGetSymbolAddress((void**)&w2l, g_w2l);

    cudaFuncSetAttribute(gemm_mma<true>,  cudaFuncAttributeMaxDynamicSharedMemorySize, SMEM_B);
    cudaFuncSetAttribute(gemm_mma<false>, cudaFuncAttributeMaxDynamicSharedMemorySize, SMEM_B);
    cudaFuncSetAttribute(attn_mma, cudaFuncAttributeMaxDynamicSharedMemorySize, AT_SMEM);

    // 0) convert x -> fp16; split w_qkv -> hi/lo; zero accumulators
    {
        int total = BATCH * C0 * HW;
        cvt_f16<<<total / 8 / 256, 256>>>(x, x16, total);
        int wtot = C3 * C0;
        split_f16<<<(wtot / 4 + 255) / 256, 256>>>(w_qkv, wqh, wql, wtot);
        zero_small<<<(BATCH * NH * HD * HD + 255) / 256, 256>>>(attn, normsq);
    }
    // 1) qkv1 = w_qkv @ x  (2-pass, fp16 out)
    {
        dim3 grid(HW / BN, (C3 + BM - 1) / BM, BATCH);
        gemm_mma<true><<<grid, 256, SMEM_B>>>(wqh, wql, x16, qkv1,
                                              C3, HW, 0, (size_t)C0 * HW,
                                              (size_t)C3 * HW);
    }
    // 2) fused depthwise 3x3 -> q,k,v fp16 + normsq
    {
        dim3 grid(HH / DW_TY, BATCH * C3);
        dwconv_fused<<<grid, dim3(DW_TX, DW_TY)>>>(qkv1, w_dw, q16, k16, v16, normsq);
    }
    // 3) tensor-core q.k^T (1-pass)
    {
        dim3 grid(AT_NSPL, BATCH * NH);
        attn_mma<<<grid, 256, AT_SMEM>>>(q16, k16, attn);
    }
    // 4) softmax
    softmax_attn<<<BATCH * NH, 64>>>(attn, normsq, ltemp);
    // 5) W2 -> fp16 hi/lo
    build_w2<<<(BATCH * C0 * C0 + 255) / 256, 256>>>(w_proj, attn, w2h, w2l);
    // 6) out = W2 @ v  (2-pass, fp32 out)
    {
        dim3 grid(HW / BN, (C0 + BM - 1) / BM, BATCH);
        gemm_mma<false><<<grid, 256, SMEM_B>>>(w2h, w2l, v16, out,
                                               C0, HW, (size_t)C0 * C0,
                                               (size_t)C0 * HW, (size_t)C0 * HW);
    }
}

// round 15
// speedup vs baseline: 1.2185x; 1.0260x over previous
#include <cuda_runtime.h>
#include <cuda_fp16.h>
#include <math.h>
#include <cstdint>

#define BATCH 2
#define C0 192
#define HH 192
#define WW 192
#define HW (HH*WW)          // 36864
#define C3 (3*C0)           // 576
#define NH 4
#define HD 48
#define KDIM 192

typedef __half fp16;

// ---------------- scratch (device globals; no allocs allowed) --------------
__device__ fp16  g_qkv1[BATCH*C3*HW];      // after 1x1 conv (fp16)
__device__ float g_normsq[BATCH*2*C0];     // [b][q|k][c]  sum of squares
__device__ float g_attn[BATCH*NH*HD*HD];   // raw dots -> softmaxed attn
__device__ fp16  g_x16[BATCH*C0*HW];       // x fp16
__device__ fp16  g_v16[BATCH*C0*HW];       // v fp16
__device__ fp16  g_k16[BATCH*C0*HW];       // k fp16
__device__ fp16  g_q16[BATCH*C0*HW];       // q fp16
__device__ fp16  g_wqh[C3*C0];             // w_qkv hi
__device__ fp16  g_wql[C3*C0];             // w_qkv lo
__device__ fp16  g_w2h[BATCH*C0*C0];       // w2 hi
__device__ fp16  g_w2l[BATCH*C0*C0];       // w2 lo

// ======================= small helpers =====================================
__device__ __forceinline__ uint32_t smem_u32(const void* p) {
    uint32_t a;
    asm("{ .reg .u64 t; cvta.to.shared.u64 t, %1; cvt.u32.u64 %0, t; }"
        : "=r"(a) : "l"(p));
    return a;
}
__device__ __forceinline__ void ldsm4(uint32_t addr, uint32_t* r) {
    asm volatile("ldmatrix.sync.aligned.m8n8.x4.shared.b16 {%0,%1,%2,%3}, [%4];"
        : "=r"(r[0]), "=r"(r[1]), "=r"(r[2]), "=r"(r[3]) : "r"(addr));
}
__device__ __forceinline__ void ldsm4t(uint32_t addr, uint32_t* r) {
    asm volatile("ldmatrix.sync.aligned.m8n8.x4.trans.shared.b16 {%0,%1,%2,%3}, [%4];"
        : "=r"(r[0]), "=r"(r[1]), "=r"(r[2]), "=r"(r[3]) : "r"(addr));
}
__device__ __forceinline__ void mma16816(float* d, const uint32_t* a, const uint32_t* b) {
    asm volatile(
        "mma.sync.aligned.m16n8k16.row.col.f32.f16.f16.f32 "
        "{%0,%1,%2,%3}, {%4,%5,%6,%7}, {%8,%9}, {%0,%1,%2,%3};"
        : "+f"(d[0]), "+f"(d[1]), "+f"(d[2]), "+f"(d[3])
        : "r"(a[0]), "r"(a[1]), "r"(a[2]), "r"(a[3]), "r"(b[0]), "r"(b[1]));
}
__device__ __forceinline__ void cpa16(uint32_t dst, const void* src, int bytes) {
    asm volatile("cp.async.cg.shared.global [%0], [%1], 16, %2;"
        :: "r"(dst), "l"(src), "r"(bytes));
}
#define CP_COMMIT() asm volatile("cp.async.commit_group;")
#define CP_WAIT(n)  asm volatile("cp.async.wait_group %0;" :: "n"(n))

__device__ __forceinline__ uint32_t pack2h(float a, float b) {
    __half2 p = __halves2half2(__float2half_rn(a), __float2half_rn(b));
    return *reinterpret_cast<uint32_t*>(&p);
}

// ======================= conversion kernels ================================
__global__ void __launch_bounds__(256) cvt_f16(
    const float* __restrict__ src, fp16* __restrict__ dst, int total)
{
    int i8 = (blockIdx.x * 256 + threadIdx.x) * 8;
    if (i8 >= total) return;
    float4 v0 = *reinterpret_cast<const float4*>(src + i8);
    float4 v1 = *reinterpret_cast<const float4*>(src + i8 + 4);
    uint4 o;
    o.x = pack2h(v0.x, v0.y); o.y = pack2h(v0.z, v0.w);
    o.z = pack2h(v1.x, v1.y); o.w = pack2h(v1.z, v1.w);
    *reinterpret_cast<uint4*>(dst + i8) = o;
}

__global__ void __launch_bounds__(256) split_f16(
    const float* __restrict__ src, fp16* __restrict__ h, fp16* __restrict__ l, int total)
{
    int i4 = (blockIdx.x * 256 + threadIdx.x) * 4;
    if (i4 >= total) return;
    float4 v = *reinterpret_cast<const float4*>(src + i4);
    fp16 h0 = __float2half_rn(v.x), h1 = __float2half_rn(v.y);
    fp16 h2 = __float2half_rn(v.z), h3 = __float2half_rn(v.w);
    float l0 = v.x - __half2float(h0), l1 = v.y - __half2float(h1);
    float l2 = v.z - __half2float(h2), l3 = v.w - __half2float(h3);
    uint2 ho, lo;
    ho.x = pack2h(__half2float(h0), __half2float(h1));
    ho.y = pack2h(__half2float(h2), __half2float(h3));
    lo.x = pack2h(l0, l1); lo.y = pack2h(l2, l3);
    *reinterpret_cast<uint2*>(h + i4) = ho;
    *reinterpret_cast<uint2*>(l + i4) = lo;
}

// ======================= tensor-core GEMM (2-pass fp16 split) ==============
// 128 threads, BM=64, BN=128, BK=32, 3-stage cp.async, 4 CTAs/SM.
// M must be a multiple of 64 (576, 192 both are).
#define BM 64
#define BN 128
#define BK 32
#define NCHUNK (KDIM/BK)     // 6
#define SA 40
#define SB 136
#define A_PLANE_B (BM*SA*2)                  // 5120
#define B_PLANE_B (BK*SB*2)                  // 8704
#define OFF_AH 0
#define OFF_AL (A_PLANE_B)
#define OFF_B  (2*A_PLANE_B)
#define BUF_B  (2*A_PLANE_B + B_PLANE_B)     // 18944
#define NSTAGE 3
#define SMEM_B (NSTAGE*BUF_B)                // 56832

template<bool HALF_OUT>
__global__ void __launch_bounds__(128) gemm_mma(
    const fp16* __restrict__ Ah, const fp16* __restrict__ Al,
    const fp16* __restrict__ B,
    void* __restrict__ Cv, int ldc,
    size_t sAb, size_t sBb, size_t sCb)
{
    extern __shared__ char smem[];
    const uint32_t sb = smem_u32(smem);
    const int tid  = threadIdx.x;
    const int wid  = tid >> 5;
    const int lane = tid & 31;
    const int warp_m = wid & 1;      // 2 m-groups of 32 rows
    const int warp_n = wid >> 1;     // 2 n-groups of 64 cols

    const int bz = blockIdx.z;
    const fp16* Ahb = Ah + bz * sAb;
    const fp16* Alb = Al + bz * sAb;
    const fp16* Bb  = B  + bz * sBb;

    const int m0 = blockIdx.y * BM;
    const int n0 = blockIdx.x * BN;

    float acc[2][8][4];
#pragma unroll
    for (int i = 0; i < 2; i++)
#pragma unroll
        for (int j = 0; j < 8; j++)
#pragma unroll
            for (int q = 0; q < 4; q++) acc[i][j][q] = 0.f;

    auto issue = [&](int kc, int buf) {
        uint32_t base = sb + buf * BUF_B;
        // A: 64 rows x 4 segs = 256 chunks per plane, 2/thread/plane
#pragma unroll
        for (int r = 0; r < 2; r++) {
            int c = tid * 2 + r;
            int row = c >> 2, seg = c & 3;
            size_t go = (size_t)(m0 + row) * KDIM + kc + seg * 8;
            uint32_t so = (uint32_t)(row * SA + seg * 8) * 2;
            cpa16(base + OFF_AH + so, Ahb + go, 16);
            cpa16(base + OFF_AL + so, Alb + go, 16);
        }
        // B: 32 rows x 16 segs = 512 chunks, 4/thread
#pragma unroll
        for (int r = 0; r < 4; r++) {
            int c = tid * 4 + r;
            int row = c >> 4, seg = c & 15;
            size_t go = (size_t)(kc + row) * HW + n0 + seg * 8;
            uint32_t so = (uint32_t)(row * SB + seg * 8) * 2;
            cpa16(base + OFF_B + so, Bb + go, 16);
        }
        CP_COMMIT();
    };

    issue(0, 0);
    issue(BK, 1);

    const int arow = warp_m * 32 + (lane & 15);
    const int acolb = (lane >> 4) * 8;
    const int brow = (lane & 7) + ((lane >> 3) & 1) * 8;
    const int bcolb = warp_n * 64 + ((lane >> 4) & 1) * 8;

    int buf = 0;
    for (int ch = 0; ch < NCHUNK; ch++) {
        if (ch < NCHUNK - 1) { CP_WAIT(1); } else { CP_WAIT(0); }
        __syncthreads();
        if (ch < NCHUNK - 2) {
            int nb = buf + 2; if (nb >= NSTAGE) nb -= NSTAGE;
            issue((ch + 2) * BK, nb);
        }

        uint32_t base = sb + buf * BUF_B;
#pragma unroll
        for (int ks = 0; ks < 2; ks++) {
            uint32_t ah[2][4], al[2][4], bh[4][4];
            int acol = ks * 16 + acolb;
#pragma unroll
            for (int mt = 0; mt < 2; mt++) {
                uint32_t ao = (uint32_t)((arow + mt * 16) * SA + acol) * 2;
                ldsm4(base + OFF_AH + ao, ah[mt]);
                ldsm4(base + OFF_AL + ao, al[mt]);
            }
            int krow = ks * 16 + brow;
#pragma unroll
            for (int p = 0; p < 4; p++) {
                uint32_t bo = (uint32_t)(krow * SB + bcolb + p * 16) * 2;
                ldsm4t(base + OFF_B + bo, bh[p]);
            }
#pragma unroll
            for (int mt = 0; mt < 2; mt++)
#pragma unroll
                for (int nt = 0; nt < 8; nt++) {
                    const uint32_t* bf = &bh[nt >> 1][(nt & 1) * 2];
                    mma16816(acc[mt][nt], ah[mt], bf);
                    mma16816(acc[mt][nt], al[mt], bf);
                }
        }
        buf++; if (buf >= NSTAGE) buf = 0;
    }

    const int erow = lane >> 2;
    const int ecol = (lane & 3) * 2;
#pragma unroll
    for (int mt = 0; mt < 2; mt++) {
        int r0 = m0 + warp_m * 32 + mt * 16 + erow;
        int r1 = r0 + 8;
#pragma unroll
        for (int nt = 0; nt < 8; nt++) {
            int cc = n0 + warp_n * 64 + nt * 8 + ecol;
            if (HALF_OUT) {
                fp16* Cb = (fp16*)Cv + bz * sCb;
                *reinterpret_cast<uint32_t*>(Cb + (size_t)r0 * ldc + cc) =
                    pack2h(acc[mt][nt][0], acc[mt][nt][1]);
                *reinterpret_cast<uint32_t*>(Cb + (size_t)r1 * ldc + cc) =
                    pack2h(acc[mt][nt][2], acc[mt][nt][3]);
            } else {
                float* Cb = (float*)Cv + bz * sCb;
                *reinterpret_cast<float2*>(Cb + (size_t)r0 * ldc + cc) =
                    make_float2(acc[mt][nt][0], acc[mt][nt][1]);
                *reinterpret_cast<float2*>(Cb + (size_t)r1 * ldc + cc) =
                    make_float2(acc[mt][nt][2], acc[mt][nt][3]);
            }
        }
    }
}

// ============ fused depthwise 3x3 (fp16 in) + q/k/v fp16 + normsq ==========
#define DW_TX 24
#define DW_TY 16
__global__ void __launch_bounds__(DW_TX*DW_TY) dwconv_fused(
    const fp16* __restrict__ in, const float* __restrict__ wdw,
    fp16* __restrict__ q16, fp16* __restrict__ k16, fp16* __restrict__ v16,
    float* __restrict__ normsq)
{
    const int bc = blockIdx.y;           // b*C3 + o
    const int b  = bc / C3;
    const int o  = bc % C3;
    const fp16* ip = in + (size_t)bc * HW;

    float w[9];
#pragma unroll
    for (int i = 0; i < 9; i++) w[i] = __ldg(wdw + o * 9 + i);

    const int y  = blockIdx.x * DW_TY + threadIdx.y;
    const int x0 = threadIdx.x * 8;

    float a[8];
#pragma unroll
    for (int i = 0; i < 8; i++) a[i] = 0.f;

#pragma unroll
    for (int dy = 0; dy < 3; dy++) {
        int yy = y + dy - 1;
        if (yy < 0 || yy >= HH) continue;
        const fp16* rp = ip + (size_t)yy * WW;
        uint4 raw = *reinterpret_cast<const uint4*>(rp + x0);
        const __half2* hh = reinterpret_cast<const __half2*>(&raw);
        float c[8];
#pragma unroll
        for (int j = 0; j < 4; j++) {
            float2 f = __half22float2(hh[j]);
            c[2*j] = f.x; c[2*j+1] = f.y;
        }
        float lft = (x0 > 0)       ? __half2float(rp[x0 - 1]) : 0.f;
        float rgt = (x0 + 8 < WW)  ? __half2float(rp[x0 + 8]) : 0.f;
        float w0 = w[dy*3], w1 = w[dy*3+1], w2 = w[dy*3+2];
        a[0] += w0*lft  + w1*c[0] + w2*c[1];
        a[1] += w0*c[0] + w1*c[1] + w2*c[2];
        a[2] += w0*c[1] + w1*c[2] + w2*c[3];
        a[3] += w0*c[2] + w1*c[3] + w2*c[4];
        a[4] += w0*c[3] + w1*c[4] + w2*c[5];
        a[5] += w0*c[4] + w1*c[5] + w2*c[6];
        a[6] += w0*c[5] + w1*c[6] + w2*c[7];
        a[7] += w0*c[6] + w1*c[7] + w2*rgt;
    }

    const int t = o / C0;                // 0=q, 1=k, 2=v
    const int c = o % C0;
    size_t off = ((size_t)b * C0 + c) * HW + (size_t)y * WW + x0;

    uint4 hv;
    hv.x = pack2h(a[0], a[1]); hv.y = pack2h(a[2], a[3]);
    hv.z = pack2h(a[4], a[5]); hv.w = pack2h(a[6], a[7]);

    fp16* dst = (t == 0) ? q16 : (t == 1) ? k16 : v16;
    *reinterpret_cast<uint4*>(dst + off) = hv;

    if (t < 2) {
        float s = 0.f;
#pragma unroll
        for (int i = 0; i < 8; i++) s += a[i] * a[i];
#pragma unroll
        for (int offm = 16; offm > 0; offm >>= 1)
            s += __shfl_xor_sync(0xffffffffu, s, offm);
        int lane = (threadIdx.y * DW_TX + threadIdx.x) & 31;
        if (lane == 0)
            atomicAdd(&normsq[(b * 2 + t) * C0 + c], s);
    }
}

// ---------------- zero attn + normsq ---------------------------------------
__global__ void zero_small(float* __restrict__ attn, float* __restrict__ normsq)
{
    int i = blockIdx.x * 256 + threadIdx.x;
    if (i < BATCH * NH * HD * HD) attn[i] = 0.f;
    if (i < BATCH * 2 * C0) normsq[i] = 0.f;
}

// ---------------- tensor-core q·k^T (1-pass fp16) --------------------------
#define AT_NSPL 18
#define AT_KBLK (HW/AT_NSPL)   // 2048
#define AT_SK 128
#define AT_SUB (AT_KBLK/AT_SK) // 16
#define AT_SROW 136
#define AT_PLANE (48*AT_SROW*2)    // 13056
#define AT_STAGE (2*AT_PLANE)      // 26112
#define AT_SMEM (2*AT_STAGE)       // 52224

__global__ void __launch_bounds__(256) attn_mma(
    const fp16* __restrict__ q16, const fp16* __restrict__ k16,
    float* __restrict__ attn)
{
    extern __shared__ char smem[];
    const uint32_t sb = smem_u32(smem);
    const int tid  = threadIdx.x;
    const int wid  = tid >> 5;
    const int lane = tid & 31;

    const int bh = blockIdx.y;
    const int b = bh / NH, h = bh % NH;
    const size_t rowbase = ((size_t)b * C0 + h * HD) * HW;
    const fp16* pl[2] = { q16 + rowbase, k16 + rowbase };
    const size_t kblk0 = (size_t)blockIdx.x * AT_KBLK;

    float acc[3][6][4];
#pragma unroll
    for (int i = 0; i < 3; i++)
#pragma unroll
        for (int j = 0; j < 6; j++)
#pragma unroll
            for (int q = 0; q < 4; q++) acc[i][j][q] = 0.f;

    auto fill = [&](int sub, int stg) {
        uint32_t base = sb + stg * AT_STAGE;
        size_t k0 = kblk0 + (size_t)sub * AT_SK;
#pragma unroll
        for (int p = 0; p < 2; p++) {
#pragma unroll
            for (int r = 0; r < 3; r++) {
                int cc = tid + r * 256;
                int row = cc >> 4, seg = cc & 15;
                cpa16(base + p * AT_PLANE + (uint32_t)(row * AT_SROW + seg * 8) * 2,
                      pl[p] + (size_t)row * HW + k0 + seg * 8, 16);
            }
        }
        CP_COMMIT();
    };

    fill(0, 0);

    const int kofs = wid * 16;
    const int a_r = lane & 15;
    const int a_c = kofs + (lane >> 4) * 8;
    const int b_r = (lane & 7) + ((lane >> 4) & 1) * 8;
    const int b_c = kofs + ((lane >> 3) & 1) * 8;

    for (int sub = 0; sub < AT_SUB; sub++) {
        CP_WAIT(0);
        __syncthreads();
        if (sub < AT_SUB - 1) fill(sub + 1, (sub + 1) & 1);

        uint32_t base = sb + (sub & 1) * AT_STAGE;
        uint32_t qf[3][4], kf[3][4];
#pragma unroll
        for (int mt = 0; mt < 3; mt++) {
            uint32_t ao = (uint32_t)((mt * 16 + a_r) * AT_SROW + a_c) * 2;
            ldsm4(base + 0 * AT_PLANE + ao, qf[mt]);
        }
#pragma unroll
        for (int nt2 = 0; nt2 < 3; nt2++) {
            uint32_t bo = (uint32_t)((nt2 * 16 + b_r) * AT_SROW + b_c) * 2;
            ldsm4(base + 1 * AT_PLANE + bo, kf[nt2]);
        }
#pragma unroll
        for (int mt = 0; mt < 3; mt++)
#pragma unroll
            for (int nt = 0; nt < 6; nt++)
                mma16816(acc[mt][nt], qf[mt], &kf[nt >> 1][(nt & 1) * 2]);
        __syncthreads();
    }

    float* red = reinterpret_cast<float*>(smem);   // [48][49]
    for (int i = tid; i < 48 * 49; i += 256) red[i] = 0.f;
    __syncthreads();
    const int erow = lane >> 2;
    const int ecol = (lane & 3) * 2;
#pragma unroll
    for (int mt = 0; mt < 3; mt++) {
        int r0 = mt * 16 + erow;
#pragma unroll
        for (int nt = 0; nt < 6; nt++) {
            int cc = nt * 8 + ecol;
            atomicAdd(&red[r0 * 49 + cc],       acc[mt][nt][0]);
            atomicAdd(&red[r0 * 49 + cc + 1],   acc[mt][nt][1]);
            atomicAdd(&red[(r0 + 8) * 49 + cc],     acc[mt][nt][2]);
            atomicAdd(&red[(r0 + 8) * 49 + cc + 1], acc[mt][nt][3]);
        }
    }
    __syncthreads();
    float* ap = attn + (size_t)bh * HD * HD;
    for (int i = tid; i < HD * HD; i += 256) {
        int r = i / HD, cl = i % HD;
        atomicAdd(&ap[i], red[r * 49 + cl]);
    }
}

// ---------------- scale by norms + temperature, softmax over e -------------
__global__ void softmax_attn(float* __restrict__ attn, const float* __restrict__ normsq,
                             const float* __restrict__ logtemp)
{
    const int bh = blockIdx.x;
    const int b = bh / NH, h = bh % NH;
    const int d = threadIdx.x;
    if (d >= HD) return;

    float lt = logtemp[h];
    float temp = (lt > 20.f ? lt : log1pf(expf(lt))) + 1e-6f;

    const float* nq = normsq + (b * 2 + 0) * C0 + h * HD;
    const float* nk = normsq + (b * 2 + 1) * C0 + h * HD;
    float* row = attn + ((size_t)bh * HD + d) * HD;
    const float qn = fmaxf(sqrtf(nq[d]), 1e-12f);

    float vals[HD];
    float mx = -1e30f;
#pragma unroll
    for (int e = 0; e < HD; e++) {
        float kn = fmaxf(sqrtf(nk[e]), 1e-12f);
        float v = row[e] / (qn * kn) * temp;
        vals[e] = v;
        mx = fmaxf(mx, v);
    }
    float s = 0.f;
#pragma unroll
    for (int e = 0; e < HD; e++) {
        vals[e] = expf(vals[e] - mx);
        s += vals[e];
    }
    float inv = 1.f / s;
#pragma unroll
    for (int e = 0; e < HD; e++) row[e] = vals[e] * inv;
}

// ---------------- W2[b] = w_proj @ blockdiag(attn[b]) -> fp16 hi/lo --------
__global__ void build_w2(const float* __restrict__ wproj, const float* __restrict__ attn,
                         fp16* __restrict__ w2h, fp16* __restrict__ w2l)
{
    int idx = blockIdx.x * 256 + threadIdx.x;
    if (idx >= BATCH * C0 * C0) return;
    int cc = idx % C0;
    int o  = (idx / C0) % C0;
    int b  = idx / (C0 * C0);
    int h = cc / HD, e = cc % HD;
    float s = 0.f;
#pragma unroll
    for (int d = 0; d < HD; d++)
        s += wproj[o * C0 + h * HD + d] * attn[(((size_t)b * NH + h) * HD + d) * HD + e];
    fp16 hi = __float2half_rn(s);
    fp16 lo = __float2half_rn(s - __half2float(hi));
    w2h[idx] = hi;
    w2l[idx] = lo;
}

// ---------------- launcher -------------------------------------------------
extern "C" void kernel_launch(void* const* d_in, const int* in_sizes, int n_in,
                              void* d_out, int out_size)
{
    const float* x      = (const float*)d_in[0];
    const float* w_qkv  = (const float*)d_in[1];
    const float* w_dw   = (const float*)d_in[2];
    const float* w_proj = (const float*)d_in[3];
    const float* ltemp  = (const float*)d_in[4];
    float* out = (float*)d_out;

    float *normsq, *attn;
    fp16 *qkv1, *x16, *v16, *k16, *q16, *wqh, *wql, *w2h, *w2l;
    cudaGetSymbolAddress((void**)&qkv1, g_qkv1);
    cudaGetSymbolAddress((void**)&normsq, g_normsq);
    cudaGetSymbolAddress((void**)&attn, g_attn);
    cudaGetSymbolAddress((void**)&x16, g_x16);
    cudaGetSymbolAddress((void**)&v16, g_v16);
    cudaGetSymbolAddress((void**)&k16, g_k16);
    cudaGetSymbolAddress((void**)&q16, g_q16);
    cudaGetSymbolAddress((void**)&wqh, g_wqh);
    cudaGetSymbolAddress((void**)&wql, g_wql);
    cudaGetSymbolAddress((void**)&w2h, g_w2h);
    cudaGetSymbolAddress((void**)&w2l, g_w2l);

    cudaFuncSetAttribute(gemm_mma<true>,  cudaFuncAttributeMaxDynamicSharedMemorySize, SMEM_B);
    cudaFuncSetAttribute(gemm_mma<false>, cudaFuncAttributeMaxDynamicSharedMemorySize, SMEM_B);
    cudaFuncSetAttribute(attn_mma, cudaFuncAttributeMaxDynamicSharedMemorySize, AT_SMEM);

    // 0) convert x -> fp16; split w_qkv -> hi/lo; zero accumulators
    {
        int total = BATCH * C0 * HW;
        cvt_f16<<<total / 8 / 256, 256>>>(x, x16, total);
        int wtot = C3 * C0;
        split_f16<<<(wtot / 4 + 255) / 256, 256>>>(w_qkv, wqh, wql, wtot);
        zero_small<<<(BATCH * NH * HD * HD + 255) / 256, 256>>>(attn, normsq);
    }
    // 1) qkv1 = w_qkv @ x  (2-pass, fp16 out)  M=576 -> 9 tiles of 64
    {
        dim3 grid(HW / BN, C3 / BM, BATCH);
        gemm_mma<true><<<grid, 128, SMEM_B>>>(wqh, wql, x16, qkv1,
                                              HW, 0, (size_t)C0 * HW,
                                              (size_t)C3 * HW);
    }
    // 2) fused depthwise 3x3 -> q,k,v fp16 + normsq
    {
        dim3 grid(HH / DW_TY, BATCH * C3);
        dwconv_fused<<<grid, dim3(DW_TX, DW_TY)>>>(qkv1, w_dw, q16, k16, v16, normsq);
    }
    // 3) tensor-core q.k^T (1-pass)
    {
        dim3 grid(AT_NSPL, BATCH * NH);
        attn_mma<<<grid, 256, AT_SMEM>>>(q16, k16, attn);
    }
    // 4) softmax
    softmax_attn<<<BATCH * NH, 64>>>(attn, normsq, ltemp);
    // 5) W2 -> fp16 hi/lo
    build_w2<<<(BATCH * C0 * C0 + 255) / 256, 256>>>(w_proj, attn, w2h, w2l);
    // 6) out = W2 @ v  (2-pass, fp32 out)  M=192 -> 3 tiles of 64
    {
        dim3 grid(HW / BN, C0 / BM, BATCH);
        gemm_mma<false><<<grid, 128, SMEM_B>>>(w2h, w2l, v16, out,
                                               HW, (size_t)C0 * C0,
                                               (size_t)C0 * HW, (size_t)C0 * HW);
    }
}

// round 16
// speedup vs baseline: 1.3667x; 1.1217x over previous
#include <cuda_runtime.h>
#include <cuda_fp16.h>
#include <math.h>
#include <cstdint>

#define BATCH 2
#define C0 192
#define HH 192
#define WW 192
#define HW (HH*WW)          // 36864
#define C3 (3*C0)           // 576
#define NH 4
#define HD 48
#define KDIM 192

typedef __half fp16;

// ---------------- scratch (device globals; no allocs allowed) --------------
__device__ fp16  g_qkv1[BATCH*C3*HW];      // after 1x1 conv (fp16)
__device__ float g_normsq[BATCH*2*C0];     // [b][q|k][c]  sum of squares
__device__ float g_attn[BATCH*NH*HD*HD];   // raw dots -> softmaxed attn
__device__ fp16  g_x16[BATCH*C0*HW];       // x fp16
__device__ fp16  g_v16[BATCH*C0*HW];       // v fp16
__device__ fp16  g_k16[BATCH*C0*HW];       // k fp16
__device__ fp16  g_q16[BATCH*C0*HW];       // q fp16
__device__ fp16  g_wq16[C3*C0];            // w_qkv fp16
__device__ fp16  g_w216[BATCH*C0*C0];      // w2 fp16

// ======================= small helpers =====================================
__device__ __forceinline__ uint32_t smem_u32(const void* p) {
    uint32_t a;
    asm("{ .reg .u64 t; cvta.to.shared.u64 t, %1; cvt.u32.u64 %0, t; }"
        : "=r"(a) : "l"(p));
    return a;
}
__device__ __forceinline__ void ldsm4(uint32_t addr, uint32_t* r) {
    asm volatile("ldmatrix.sync.aligned.m8n8.x4.shared.b16 {%0,%1,%2,%3}, [%4];"
        : "=r"(r[0]), "=r"(r[1]), "=r"(r[2]), "=r"(r[3]) : "r"(addr));
}
__device__ __forceinline__ void ldsm4t(uint32_t addr, uint32_t* r) {
    asm volatile("ldmatrix.sync.aligned.m8n8.x4.trans.shared.b16 {%0,%1,%2,%3}, [%4];"
        : "=r"(r[0]), "=r"(r[1]), "=r"(r[2]), "=r"(r[3]) : "r"(addr));
}
__device__ __forceinline__ void mma16816(float* d, const uint32_t* a, const uint32_t* b) {
    asm volatile(
        "mma.sync.aligned.m16n8k16.row.col.f32.f16.f16.f32 "
        "{%0,%1,%2,%3}, {%4,%5,%6,%7}, {%8,%9}, {%0,%1,%2,%3};"
        : "+f"(d[0]), "+f"(d[1]), "+f"(d[2]), "+f"(d[3])
        : "r"(a[0]), "r"(a[1]), "r"(a[2]), "r"(a[3]), "r"(b[0]), "r"(b[1]));
}
__device__ __forceinline__ void cpa16(uint32_t dst, const void* src, int bytes) {
    asm volatile("cp.async.cg.shared.global [%0], [%1], 16, %2;"
        :: "r"(dst), "l"(src), "r"(bytes));
}
#define CP_COMMIT() asm volatile("cp.async.commit_group;")
#define CP_WAIT(n)  asm volatile("cp.async.wait_group %0;" :: "n"(n))

__device__ __forceinline__ uint32_t pack2h(float a, float b) {
    __half2 p = __halves2half2(__float2half_rn(a), __float2half_rn(b));
    return *reinterpret_cast<uint32_t*>(&p);
}

// ======================= conversion kernel =================================
__global__ void __launch_bounds__(256) cvt_f16(
    const float* __restrict__ src, fp16* __restrict__ dst, int total)
{
    int i8 = (blockIdx.x * 256 + threadIdx.x) * 8;
    if (i8 >= total) return;
    float4 v0 = *reinterpret_cast<const float4*>(src + i8);
    float4 v1 = *reinterpret_cast<const float4*>(src + i8 + 4);
    uint4 o;
    o.x = pack2h(v0.x, v0.y); o.y = pack2h(v0.z, v0.w);
    o.z = pack2h(v1.x, v1.y); o.w = pack2h(v1.z, v1.w);
    *reinterpret_cast<uint4*>(dst + i8) = o;
}

// ======================= tensor-core GEMM (1-pass fp16, R15 skeleton) ======
// 128 threads, BM=64, BN=128, BK=32, 3-stage cp.async, 4 CTAs/SM.
// M must be a multiple of 64 (576, 192 both are).
#define BM 64
#define BN 128
#define BK 32
#define NCHUNK (KDIM/BK)     // 6
#define SA 40
#define SB 136
#define A_PLANE_B (BM*SA*2)                  // 5120
#define B_PLANE_B (BK*SB*2)                  // 8704
#define OFF_A 0
#define OFF_B (A_PLANE_B)
#define BUF_B (A_PLANE_B + B_PLANE_B)        // 13824
#define NSTAGE 3
#define SMEM_B (NSTAGE*BUF_B)                // 41472

template<bool HALF_OUT>
__global__ void __launch_bounds__(128) gemm_mma(
    const fp16* __restrict__ A, const fp16* __restrict__ B,
    void* __restrict__ Cv, int ldc,
    size_t sAb, size_t sBb, size_t sCb)
{
    extern __shared__ char smem[];
    const uint32_t sb = smem_u32(smem);
    const int tid  = threadIdx.x;
    const int wid  = tid >> 5;
    const int lane = tid & 31;
    const int warp_m = wid & 1;      // 2 m-groups of 32 rows
    const int warp_n = wid >> 1;     // 2 n-groups of 64 cols

    const int bz = blockIdx.z;
    const fp16* Ab = A + bz * sAb;
    const fp16* Bb = B + bz * sBb;

    const int m0 = blockIdx.y * BM;
    const int n0 = blockIdx.x * BN;

    float acc[2][8][4];
#pragma unroll
    for (int i = 0; i < 2; i++)
#pragma unroll
        for (int j = 0; j < 8; j++)
#pragma unroll
            for (int q = 0; q < 4; q++) acc[i][j][q] = 0.f;

    auto issue = [&](int kc, int buf) {
        uint32_t base = sb + buf * BUF_B;
        // A: 64 rows x 4 segs = 256 chunks, 2/thread
#pragma unroll
        for (int r = 0; r < 2; r++) {
            int c = tid * 2 + r;
            int row = c >> 2, seg = c & 3;
            size_t go = (size_t)(m0 + row) * KDIM + kc + seg * 8;
            uint32_t so = (uint32_t)(row * SA + seg * 8) * 2;
            cpa16(base + OFF_A + so, Ab + go, 16);
        }
        // B: 32 rows x 16 segs = 512 chunks, 4/thread
#pragma unroll
        for (int r = 0; r < 4; r++) {
            int c = tid * 4 + r;
            int row = c >> 4, seg = c & 15;
            size_t go = (size_t)(kc + row) * HW + n0 + seg * 8;
            uint32_t so = (uint32_t)(row * SB + seg * 8) * 2;
            cpa16(base + OFF_B + so, Bb + go, 16);
        }
        CP_COMMIT();
    };

    issue(0, 0);
    issue(BK, 1);

    const int arow = warp_m * 32 + (lane & 15);
    const int acolb = (lane >> 4) * 8;
    const int brow = (lane & 7) + ((lane >> 3) & 1) * 8;
    const int bcolb = warp_n * 64 + ((lane >> 4) & 1) * 8;

    int buf = 0;
    for (int ch = 0; ch < NCHUNK; ch++) {
        if (ch < NCHUNK - 1) { CP_WAIT(1); } else { CP_WAIT(0); }
        __syncthreads();
        if (ch < NCHUNK - 2) {
            int nb = buf + 2; if (nb >= NSTAGE) nb -= NSTAGE;
            issue((ch + 2) * BK, nb);
        }

        uint32_t base = sb + buf * BUF_B;
#pragma unroll
        for (int ks = 0; ks < 2; ks++) {
            uint32_t af[2][4], bf[4][4];
            int acol = ks * 16 + acolb;
#pragma unroll
            for (int mt = 0; mt < 2; mt++) {
                uint32_t ao = (uint32_t)((arow + mt * 16) * SA + acol) * 2;
                ldsm4(base + OFF_A + ao, af[mt]);
            }
            int krow = ks * 16 + brow;
#pragma unroll
            for (int p = 0; p < 4; p++) {
                uint32_t bo = (uint32_t)(krow * SB + bcolb + p * 16) * 2;
                ldsm4t(base + OFF_B + bo, bf[p]);
            }
#pragma unroll
            for (int mt = 0; mt < 2; mt++)
#pragma unroll
                for (int nt = 0; nt < 8; nt++)
                    mma16816(acc[mt][nt], af[mt], &bf[nt >> 1][(nt & 1) * 2]);
        }
        buf++; if (buf >= NSTAGE) buf = 0;
    }

    const int erow = lane >> 2;
    const int ecol = (lane & 3) * 2;
#pragma unroll
    for (int mt = 0; mt < 2; mt++) {
        int r0 = m0 + warp_m * 32 + mt * 16 + erow;
        int r1 = r0 + 8;
#pragma unroll
        for (int nt = 0; nt < 8; nt++) {
            int cc = n0 + warp_n * 64 + nt * 8 + ecol;
            if (HALF_OUT) {
                fp16* Cb = (fp16*)Cv + bz * sCb;
                *reinterpret_cast<uint32_t*>(Cb + (size_t)r0 * ldc + cc) =
                    pack2h(acc[mt][nt][0], acc[mt][nt][1]);
                *reinterpret_cast<uint32_t*>(Cb + (size_t)r1 * ldc + cc) =
                    pack2h(acc[mt][nt][2], acc[mt][nt][3]);
            } else {
                float* Cb = (float*)Cv + bz * sCb;
                *reinterpret_cast<float2*>(Cb + (size_t)r0 * ldc + cc) =
                    make_float2(acc[mt][nt][0], acc[mt][nt][1]);
                *reinterpret_cast<float2*>(Cb + (size_t)r1 * ldc + cc) =
                    make_float2(acc[mt][nt][2], acc[mt][nt][3]);
            }
        }
    }
}

// ============ fused depthwise 3x3 (fp16 in) + q/k/v fp16 + normsq ==========
#define DW_TX 24
#define DW_TY 16
__global__ void __launch_bounds__(DW_TX*DW_TY) dwconv_fused(
    const fp16* __restrict__ in, const float* __restrict__ wdw,
    fp16* __restrict__ q16, fp16* __restrict__ k16, fp16* __restrict__ v16,
    float* __restrict__ normsq)
{
    const int bc = blockIdx.y;           // b*C3 + o
    const int b  = bc / C3;
    const int o  = bc % C3;
    const fp16* ip = in + (size_t)bc * HW;

    float w[9];
#pragma unroll
    for (int i = 0; i < 9; i++) w[i] = __ldg(wdw + o * 9 + i);

    const int y  = blockIdx.x * DW_TY + threadIdx.y;
    const int x0 = threadIdx.x * 8;

    float a[8];
#pragma unroll
    for (int i = 0; i < 8; i++) a[i] = 0.f;

#pragma unroll
    for (int dy = 0; dy < 3; dy++) {
        int yy = y + dy - 1;
        if (yy < 0 || yy >= HH) continue;
        const fp16* rp = ip + (size_t)yy * WW;
        uint4 raw = *reinterpret_cast<const uint4*>(rp + x0);
        const __half2* hh = reinterpret_cast<const __half2*>(&raw);
        float c[8];
#pragma unroll
        for (int j = 0; j < 4; j++) {
            float2 f = __half22float2(hh[j]);
            c[2*j] = f.x; c[2*j+1] = f.y;
        }
        float lft = (x0 > 0)       ? __half2float(rp[x0 - 1]) : 0.f;
        float rgt = (x0 + 8 < WW)  ? __half2float(rp[x0 + 8]) : 0.f;
        float w0 = w[dy*3], w1 = w[dy*3+1], w2 = w[dy*3+2];
        a[0] += w0*lft  + w1*c[0] + w2*c[1];
        a[1] += w0*c[0] + w1*c[1] + w2*c[2];
        a[2] += w0*c[1] + w1*c[2] + w2*c[3];
        a[3] += w0*c[2] + w1*c[3] + w2*c[4];
        a[4] += w0*c[3] + w1*c[4] + w2*c[5];
        a[5] += w0*c[4] + w1*c[5] + w2*c[6];
        a[6] += w0*c[5] + w1*c[6] + w2*c[7];
        a[7] += w0*c[6] + w1*c[7] + w2*rgt;
    }

    const int t = o / C0;                // 0=q, 1=k, 2=v
    const int c = o % C0;
    size_t off = ((size_t)b * C0 + c) * HW + (size_t)y * WW + x0;

    uint4 hv;
    hv.x = pack2h(a[0], a[1]); hv.y = pack2h(a[2], a[3]);
    hv.z = pack2h(a[4], a[5]); hv.w = pack2h(a[6], a[7]);

    fp16* dst = (t == 0) ? q16 : (t == 1) ? k16 : v16;
    *reinterpret_cast<uint4*>(dst + off) = hv;

    if (t < 2) {
        float s = 0.f;
#pragma unroll
        for (int i = 0; i < 8; i++) s += a[i] * a[i];
#pragma unroll
        for (int offm = 16; offm > 0; offm >>= 1)
            s += __shfl_xor_sync(0xffffffffu, s, offm);
        int lane = (threadIdx.y * DW_TX + threadIdx.x) & 31;
        if (lane == 0)
            atomicAdd(&normsq[(b * 2 + t) * C0 + c], s);
    }
}

// ---------------- zero attn + normsq ---------------------------------------
__global__ void zero_small(float* __restrict__ attn, float* __restrict__ normsq)
{
    int i = blockIdx.x * 256 + threadIdx.x;
    if (i < BATCH * NH * HD * HD) attn[i] = 0.f;
    if (i < BATCH * 2 * C0) normsq[i] = 0.f;
}

// ---------------- tensor-core q·k^T (1-pass fp16) --------------------------
#define AT_NSPL 18
#define AT_KBLK (HW/AT_NSPL)   // 2048
#define AT_SK 128
#define AT_SUB (AT_KBLK/AT_SK) // 16
#define AT_SROW 136
#define AT_PLANE (48*AT_SROW*2)    // 13056
#define AT_STAGE (2*AT_PLANE)      // 26112
#define AT_SMEM (2*AT_STAGE)       // 52224

__global__ void __launch_bounds__(256) attn_mma(
    const fp16* __restrict__ q16, const fp16* __restrict__ k16,
    float* __restrict__ attn)
{
    extern __shared__ char smem[];
    const uint32_t sb = smem_u32(smem);
    const int tid  = threadIdx.x;
    const int wid  = tid >> 5;
    const int lane = tid & 31;

    const int bh = blockIdx.y;
    const int b = bh / NH, h = bh % NH;
    const size_t rowbase = ((size_t)b * C0 + h * HD) * HW;
    const fp16* pl[2] = { q16 + rowbase, k16 + rowbase };
    const size_t kblk0 = (size_t)blockIdx.x * AT_KBLK;

    float acc[3][6][4];
#pragma unroll
    for (int i = 0; i < 3; i++)
#pragma unroll
        for (int j = 0; j < 6; j++)
#pragma unroll
            for (int q = 0; q < 4; q++) acc[i][j][q] = 0.f;

    auto fill = [&](int sub, int stg) {
        uint32_t base = sb + stg * AT_STAGE;
        size_t k0 = kblk0 + (size_t)sub * AT_SK;
#pragma unroll
        for (int p = 0; p < 2; p++) {
#pragma unroll
            for (int r = 0; r < 3; r++) {
                int cc = tid + r * 256;
                int row = cc >> 4, seg = cc & 15;
                cpa16(base + p * AT_PLANE + (uint32_t)(row * AT_SROW + seg * 8) * 2,
                      pl[p] + (size_t)row * HW + k0 + seg * 8, 16);
            }
        }
        CP_COMMIT();
    };

    fill(0, 0);

    const int kofs = wid * 16;
    const int a_r = lane & 15;
    const int a_c = kofs + (lane >> 4) * 8;
    const int b_r = (lane & 7) + ((lane >> 4) & 1) * 8;
    const int b_c = kofs + ((lane >> 3) & 1) * 8;

    for (int sub = 0; sub < AT_SUB; sub++) {
        CP_WAIT(0);
        __syncthreads();
        if (sub < AT_SUB - 1) fill(sub + 1, (sub + 1) & 1);

        uint32_t base = sb + (sub & 1) * AT_STAGE;
        uint32_t qf[3][4], kf[3][4];
#pragma unroll
        for (int mt = 0; mt < 3; mt++) {
            uint32_t ao = (uint32_t)((mt * 16 + a_r) * AT_SROW + a_c) * 2;
            ldsm4(base + 0 * AT_PLANE + ao, qf[mt]);
        }
#pragma unroll
        for (int nt2 = 0; nt2 < 3; nt2++) {
            uint32_t bo = (uint32_t)((nt2 * 16 + b_r) * AT_SROW + b_c) * 2;
            ldsm4(base + 1 * AT_PLANE + bo, kf[nt2]);
        }
#pragma unroll
        for (int mt = 0; mt < 3; mt++)
#pragma unroll
            for (int nt = 0; nt < 6; nt++)
                mma16816(acc[mt][nt], qf[mt], &kf[nt >> 1][(nt & 1) * 2]);
        __syncthreads();
    }

    float* red = reinterpret_cast<float*>(smem);   // [48][49]
    for (int i = tid; i < 48 * 49; i += 256) red[i] = 0.f;
    __syncthreads();
    const int erow = lane >> 2;
    const int ecol = (lane & 3) * 2;
#pragma unroll
    for (int mt = 0; mt < 3; mt++) {
        int r0 = mt * 16 + erow;
#pragma unroll
        for (int nt = 0; nt < 6; nt++) {
            int cc = nt * 8 + ecol;
            atomicAdd(&red[r0 * 49 + cc],       acc[mt][nt][0]);
            atomicAdd(&red[r0 * 49 + cc + 1],   acc[mt][nt][1]);
            atomicAdd(&red[(r0 + 8) * 49 + cc],     acc[mt][nt][2]);
            atomicAdd(&red[(r0 + 8) * 49 + cc + 1], acc[mt][nt][3]);
        }
    }
    __syncthreads();
    float* ap = attn + (size_t)bh * HD * HD;
    for (int i = tid; i < HD * HD; i += 256) {
        int r = i / HD, cl = i % HD;
        atomicAdd(&ap[i], red[r * 49 + cl]);
    }
}

// ---------------- scale by norms + temperature, softmax over e -------------
__global__ void softmax_attn(float* __restrict__ attn, const float* __restrict__ normsq,
                             const float* __restrict__ logtemp)
{
    const int bh = blockIdx.x;
    const int b = bh / NH, h = bh % NH;
    const int d = threadIdx.x;
    if (d >= HD) return;

    float lt = logtemp[h];
    float temp = (lt > 20.f ? lt : log1pf(expf(lt))) + 1e-6f;

    const float* nq = normsq + (b * 2 + 0) * C0 + h * HD;
    const float* nk = normsq + (b * 2 + 1) * C0 + h * HD;
    float* row = attn + ((size_t)bh * HD + d) * HD;
    const float qn = fmaxf(sqrtf(nq[d]), 1e-12f);

    float vals[HD];
    float mx = -1e30f;
#pragma unroll
    for (int e = 0; e < HD; e++) {
        float kn = fmaxf(sqrtf(nk[e]), 1e-12f);
        float v = row[e] / (qn * kn) * temp;
        vals[e] = v;
        mx = fmaxf(mx, v);
    }
    float s = 0.f;
#pragma unroll
    for (int e = 0; e < HD; e++) {
        vals[e] = expf(vals[e] - mx);
        s += vals[e];
    }
    float inv = 1.f / s;
#pragma unroll
    for (int e = 0; e < HD; e++) row[e] = vals[e] * inv;
}

// ---------------- W2[b] = w_proj @ blockdiag(attn[b]) -> fp16 --------------
__global__ void build_w2(const float* __restrict__ wproj, const float* __restrict__ attn,
                         fp16* __restrict__ w2)
{
    int idx = blockIdx.x * 256 + threadIdx.x;
    if (idx >= BATCH * C0 * C0) return;
    int cc = idx % C0;
    int o  = (idx / C0) % C0;
    int b  = idx / (C0 * C0);
    int h = cc / HD, e = cc % HD;
    float s = 0.f;
#pragma unroll
    for (int d = 0; d < HD; d++)
        s += wproj[o * C0 + h * HD + d] * attn[(((size_t)b * NH + h) * HD + d) * HD + e];
    w2[idx] = __float2half_rn(s);
}

// ---------------- launcher -------------------------------------------------
extern "C" void kernel_launch(void* const* d_in, const int* in_sizes, int n_in,
                              void* d_out, int out_size)
{
    const float* x      = (const float*)d_in[0];
    const float* w_qkv  = (const float*)d_in[1];
    const float* w_dw   = (const float*)d_in[2];
    const float* w_proj = (const float*)d_in[3];
    const float* ltemp  = (const float*)d_in[4];
    float* out = (float*)d_out;

    float *normsq, *attn;
    fp16 *qkv1, *x16, *v16, *k16, *q16, *wq16, *w216;
    cudaGetSymbolAddress((void**)&qkv1, g_qkv1);
    cudaGetSymbolAddress((void**)&normsq, g_normsq);
    cudaGetSymbolAddress((void**)&attn, g_attn);
    cudaGetSymbolAddress((void**)&x16, g_x16);
    cudaGetSymbolAddress((void**)&v16, g_v16);
    cudaGetSymbolAddress((void**)&k16, g_k16);
    cudaGetSymbolAddress((void**)&q16, g_q16);
    cudaGetSymbolAddress((void**)&wq16, g_wq16);
    cudaGetSymbolAddress((void**)&w216, g_w216);

    cudaFuncSetAttribute(gemm_mma<true>,  cudaFuncAttributeMaxDynamicSharedMemorySize, SMEM_B);
    cudaFuncSetAttribute(gemm_mma<false>, cudaFuncAttributeMaxDynamicSharedMemorySize, SMEM_B);
    cudaFuncSetAttribute(attn_mma, cudaFuncAttributeMaxDynamicSharedMemorySize, AT_SMEM);

    // 0) convert x, w_qkv -> fp16; zero accumulators
    {
        int total = BATCH * C0 * HW;
        cvt_f16<<<total / 8 / 256, 256>>>(x, x16, total);
        int wtot = C3 * C0;
        cvt_f16<<<(wtot / 8 + 255) / 256, 256>>>(w_qkv, wq16, wtot);
        zero_small<<<(BATCH * NH * HD * HD + 255) / 256, 256>>>(attn, normsq);
    }
    // 1) qkv1 = w_qkv @ x  (1-pass, fp16 out)  M=576 -> 9 tiles of 64
    {
        dim3 grid(HW / BN, C3 / BM, BATCH);
        gemm_mma<true><<<grid, 128, SMEM_B>>>(wq16, x16, qkv1,
                                              HW, 0, (size_t)C0 * HW,
                                              (size_t)C3 * HW);
    }
    // 2) fused depthwise 3x3 -> q,k,v fp16 + normsq
    {
        dim3 grid(HH / DW_TY, BATCH * C3);
        dwconv_fused<<<grid, dim3(DW_TX, DW_TY)>>>(qkv1, w_dw, q16, k16, v16, normsq);
    }
    // 3) tensor-core q.k^T (1-pass)
    {
        dim3 grid(AT_NSPL, BATCH * NH);
        attn_mma<<<grid, 256, AT_SMEM>>>(q16, k16, attn);
    }
    // 4) softmax
    softmax_attn<<<BATCH * NH, 64>>>(attn, normsq, ltemp);
    // 5) W2 -> fp16
    build_w2<<<(BATCH * C0 * C0 + 255) / 256, 256>>>(w_proj, attn, w216);
    // 6) out = W2 @ v  (1-pass, fp32 out)  M=192 -> 3 tiles of 64
    {
        dim3 grid(HW / BN, C0 / BM, BATCH);
        gemm_mma<false><<<grid, 128, SMEM_B>>>(w216, v16, out,
                                               HW, (size_t)C0 * C0,
                                               (size_t)C0 * HW, (size_t)C0 * HW);
    }
}

// round 17
// speedup vs baseline: 1.3817x; 1.0110x over previous
#include <cuda_runtime.h>
#include <cuda_fp16.h>
#include <math.h>
#include <cstdint>

#define BATCH 2
#define C0 192
#define HH 192
#define WW 192
#define HW (HH*WW)          // 36864
#define C3 (3*C0)           // 576
#define NH 4
#define HD 48
#define KDIM 192

typedef __half fp16;

// ---------------- scratch (device globals; no allocs allowed) --------------
__device__ fp16  g_qkv1[BATCH*C3*HW];      // after 1x1 conv (fp16)
__device__ float g_normsq[BATCH*2*C0];     // [b][q|k][c]  sum of squares
__device__ float g_attn[BATCH*NH*HD*HD];   // raw dots -> softmaxed attn
__device__ fp16  g_x16[BATCH*C0*HW];       // x fp16
__device__ fp16  g_v16[BATCH*C0*HW];       // v fp16
__device__ fp16  g_k16[BATCH*C0*HW];       // k fp16
__device__ fp16  g_q16[BATCH*C0*HW];       // q fp16
__device__ fp16  g_wq16[C3*C0];            // w_qkv fp16
__device__ fp16  g_w216[BATCH*C0*C0];      // w2 fp16

// ======================= small helpers =====================================
__device__ __forceinline__ uint32_t smem_u32(const void* p) {
    uint32_t a;
    asm("{ .reg .u64 t; cvta.to.shared.u64 t, %1; cvt.u32.u64 %0, t; }"
        : "=r"(a) : "l"(p));
    return a;
}
__device__ __forceinline__ void ldsm4(uint32_t addr, uint32_t* r) {
    asm volatile("ldmatrix.sync.aligned.m8n8.x4.shared.b16 {%0,%1,%2,%3}, [%4];"
        : "=r"(r[0]), "=r"(r[1]), "=r"(r[2]), "=r"(r[3]) : "r"(addr));
}
__device__ __forceinline__ void ldsm4t(uint32_t addr, uint32_t* r) {
    asm volatile("ldmatrix.sync.aligned.m8n8.x4.trans.shared.b16 {%0,%1,%2,%3}, [%4];"
        : "=r"(r[0]), "=r"(r[1]), "=r"(r[2]), "=r"(r[3]) : "r"(addr));
}
__device__ __forceinline__ void mma16816(float* d, const uint32_t* a, const uint32_t* b) {
    asm volatile(
        "mma.sync.aligned.m16n8k16.row.col.f32.f16.f16.f32 "
        "{%0,%1,%2,%3}, {%4,%5,%6,%7}, {%8,%9}, {%0,%1,%2,%3};"
        : "+f"(d[0]), "+f"(d[1]), "+f"(d[2]), "+f"(d[3])
        : "r"(a[0]), "r"(a[1]), "r"(a[2]), "r"(a[3]), "r"(b[0]), "r"(b[1]));
}
__device__ __forceinline__ void cpa16(uint32_t dst, const void* src, int bytes) {
    asm volatile("cp.async.cg.shared.global [%0], [%1], 16, %2;"
        :: "r"(dst), "l"(src), "r"(bytes));
}
#define CP_COMMIT() asm volatile("cp.async.commit_group;")
#define CP_WAIT(n)  asm volatile("cp.async.wait_group %0;" :: "n"(n))

__device__ __forceinline__ uint32_t pack2h(float a, float b) {
    __half2 p = __halves2half2(__float2half_rn(a), __float2half_rn(b));
    return *reinterpret_cast<uint32_t*>(&p);
}

// ======================= conversion kernel =================================
__global__ void __launch_bounds__(256) cvt_f16(
    const float* __restrict__ src, fp16* __restrict__ dst, int total)
{
    int i8 = (blockIdx.x * 256 + threadIdx.x) * 8;
    if (i8 >= total) return;
    float4 v0 = *reinterpret_cast<const float4*>(src + i8);
    float4 v1 = *reinterpret_cast<const float4*>(src + i8 + 4);
    uint4 o;
    o.x = pack2h(v0.x, v0.y); o.y = pack2h(v0.z, v0.w);
    o.z = pack2h(v1.x, v1.y); o.w = pack2h(v1.z, v1.w);
    *reinterpret_cast<uint4*>(dst + i8) = o;
}

// ======================= tensor-core GEMM (1-pass fp16) ====================
// 128 threads, BM=64, BN=128, BK=32, 3-stage cp.async, regs pinned for
// 4 CTAs/SM.
#define BM 64
#define BN 128
#define BK 32
#define NCHUNK (KDIM/BK)     // 6
#define SA 40
#define SB 136
#define A_PLANE_B (BM*SA*2)                  // 5120
#define B_PLANE_B (BK*SB*2)                  // 8704
#define OFF_A 0
#define OFF_B (A_PLANE_B)
#define BUF_B (A_PLANE_B + B_PLANE_B)        // 13824
#define NSTAGE 3
#define SMEM_B (NSTAGE*BUF_B)                // 41472

template<bool HALF_OUT>
__global__ void __launch_bounds__(128, 4) gemm_mma(
    const fp16* __restrict__ A, const fp16* __restrict__ B,
    void* __restrict__ Cv, int ldc,
    size_t sAb, size_t sBb, size_t sCb)
{
    extern __shared__ char smem[];
    const uint32_t sb = smem_u32(smem);
    const int tid  = threadIdx.x;
    const int wid  = tid >> 5;
    const int lane = tid & 31;
    const int warp_m = wid & 1;      // 2 m-groups of 32 rows
    const int warp_n = wid >> 1;     // 2 n-groups of 64 cols

    const int bz = blockIdx.z;
    const fp16* Ab = A + bz * sAb;
    const fp16* Bb = B + bz * sBb;

    const int m0 = blockIdx.y * BM;
    const int n0 = blockIdx.x * BN;

    float acc[2][8][4];
#pragma unroll
    for (int i = 0; i < 2; i++)
#pragma unroll
        for (int j = 0; j < 8; j++)
#pragma unroll
            for (int q = 0; q < 4; q++) acc[i][j][q] = 0.f;

    auto issue = [&](int kc, int buf) {
        uint32_t base = sb + buf * BUF_B;
        // A: 64 rows x 4 segs = 256 chunks, 2/thread
#pragma unroll
        for (int r = 0; r < 2; r++) {
            int c = tid * 2 + r;
            int row = c >> 2, seg = c & 3;
            size_t go = (size_t)(m0 + row) * KDIM + kc + seg * 8;
            uint32_t so = (uint32_t)(row * SA + seg * 8) * 2;
            cpa16(base + OFF_A + so, Ab + go, 16);
        }
        // B: 32 rows x 16 segs = 512 chunks, 4/thread
#pragma unroll
        for (int r = 0; r < 4; r++) {
            int c = tid * 4 + r;
            int row = c >> 4, seg = c & 15;
            size_t go = (size_t)(kc + row) * HW + n0 + seg * 8;
            uint32_t so = (uint32_t)(row * SB + seg * 8) * 2;
            cpa16(base + OFF_B + so, Bb + go, 16);
        }
        CP_COMMIT();
    };

    issue(0, 0);
    issue(BK, 1);

    const int arow = warp_m * 32 + (lane & 15);
    const int acolb = (lane >> 4) * 8;
    const int brow = (lane & 7) + ((lane >> 3) & 1) * 8;
    const int bcolb = warp_n * 64 + ((lane >> 4) & 1) * 8;

    int buf = 0;
    for (int ch = 0; ch < NCHUNK; ch++) {
        if (ch < NCHUNK - 1) { CP_WAIT(1); } else { CP_WAIT(0); }
        __syncthreads();
        if (ch < NCHUNK - 2) {
            int nb = buf + 2; if (nb >= NSTAGE) nb -= NSTAGE;
            issue((ch + 2) * BK, nb);
        }

        uint32_t base = sb + buf * BUF_B;
#pragma unroll
        for (int ks = 0; ks < 2; ks++) {
            uint32_t af[2][4], bf[4][4];
            int acol = ks * 16 + acolb;
#pragma unroll
            for (int mt = 0; mt < 2; mt++) {
                uint32_t ao = (uint32_t)((arow + mt * 16) * SA + acol) * 2;
                ldsm4(base + OFF_A + ao, af[mt]);
            }
            int krow = ks * 16 + brow;
#pragma unroll
            for (int p = 0; p < 4; p++) {
                uint32_t bo = (uint32_t)(krow * SB + bcolb + p * 16) * 2;
                ldsm4t(base + OFF_B + bo, bf[p]);
            }
#pragma unroll
            for (int mt = 0; mt < 2; mt++)
#pragma unroll
                for (int nt = 0; nt < 8; nt++)
                    mma16816(acc[mt][nt], af[mt], &bf[nt >> 1][(nt & 1) * 2]);
        }
        buf++; if (buf >= NSTAGE) buf = 0;
    }

    const int erow = lane >> 2;
    const int ecol = (lane & 3) * 2;
#pragma unroll
    for (int mt = 0; mt < 2; mt++) {
        int r0 = m0 + warp_m * 32 + mt * 16 + erow;
        int r1 = r0 + 8;
#pragma unroll
        for (int nt = 0; nt < 8; nt++) {
            int cc = n0 + warp_n * 64 + nt * 8 + ecol;
            if (HALF_OUT) {
                fp16* Cb = (fp16*)Cv + bz * sCb;
                *reinterpret_cast<uint32_t*>(Cb + (size_t)r0 * ldc + cc) =
                    pack2h(acc[mt][nt][0], acc[mt][nt][1]);
                *reinterpret_cast<uint32_t*>(Cb + (size_t)r1 * ldc + cc) =
                    pack2h(acc[mt][nt][2], acc[mt][nt][3]);
            } else {
                float* Cb = (float*)Cv + bz * sCb;
                *reinterpret_cast<float2*>(Cb + (size_t)r0 * ldc + cc) =
                    make_float2(acc[mt][nt][0], acc[mt][nt][1]);
                *reinterpret_cast<float2*>(Cb + (size_t)r1 * ldc + cc) =
                    make_float2(acc[mt][nt][2], acc[mt][nt][3]);
            }
        }
    }
}

// ============ fused depthwise 3x3 (fp16 in) + q/k/v fp16 + normsq ==========
#define DW_TX 24
#define DW_TY 16
__global__ void __launch_bounds__(DW_TX*DW_TY) dwconv_fused(
    const fp16* __restrict__ in, const float* __restrict__ wdw,
    fp16* __restrict__ q16, fp16* __restrict__ k16, fp16* __restrict__ v16,
    float* __restrict__ normsq)
{
    const int bc = blockIdx.y;           // b*C3 + o
    const int b  = bc / C3;
    const int o  = bc % C3;
    const fp16* ip = in + (size_t)bc * HW;

    float w[9];
#pragma unroll
    for (int i = 0; i < 9; i++) w[i] = __ldg(wdw + o * 9 + i);

    const int y  = blockIdx.x * DW_TY + threadIdx.y;
    const int x0 = threadIdx.x * 8;

    float a[8];
#pragma unroll
    for (int i = 0; i < 8; i++) a[i] = 0.f;

#pragma unroll
    for (int dy = 0; dy < 3; dy++) {
        int yy = y + dy - 1;
        if (yy < 0 || yy >= HH) continue;
        const fp16* rp = ip + (size_t)yy * WW;
        uint4 raw = *reinterpret_cast<const uint4*>(rp + x0);
        const __half2* hh = reinterpret_cast<const __half2*>(&raw);
        float c[8];
#pragma unroll
        for (int j = 0; j < 4; j++) {
            float2 f = __half22float2(hh[j]);
            c[2*j] = f.x; c[2*j+1] = f.y;
        }
        float lft = (x0 > 0)       ? __half2float(rp[x0 - 1]) : 0.f;
        float rgt = (x0 + 8 < WW)  ? __half2float(rp[x0 + 8]) : 0.f;
        float w0 = w[dy*3], w1 = w[dy*3+1], w2 = w[dy*3+2];
        a[0] += w0*lft  + w1*c[0] + w2*c[1];
        a[1] += w0*c[0] + w1*c[1] + w2*c[2];
        a[2] += w0*c[1] + w1*c[2] + w2*c[3];
        a[3] += w0*c[2] + w1*c[3] + w2*c[4];
        a[4] += w0*c[3] + w1*c[4] + w2*c[5];
        a[5] += w0*c[4] + w1*c[5] + w2*c[6];
        a[6] += w0*c[5] + w1*c[6] + w2*c[7];
        a[7] += w0*c[6] + w1*c[7] + w2*rgt;
    }

    const int t = o / C0;                // 0=q, 1=k, 2=v
    const int c = o % C0;
    size_t off = ((size_t)b * C0 + c) * HW + (size_t)y * WW + x0;

    uint4 hv;
    hv.x = pack2h(a[0], a[1]); hv.y = pack2h(a[2], a[3]);
    hv.z = pack2h(a[4], a[5]); hv.w = pack2h(a[6], a[7]);

    fp16* dst = (t == 0) ? q16 : (t == 1) ? k16 : v16;
    *reinterpret_cast<uint4*>(dst + off) = hv;

    if (t < 2) {
        float s = 0.f;
#pragma unroll
        for (int i = 0; i < 8; i++) s += a[i] * a[i];
#pragma unroll
        for (int offm = 16; offm > 0; offm >>= 1)
            s += __shfl_xor_sync(0xffffffffu, s, offm);
        int lane = (threadIdx.y * DW_TX + threadIdx.x) & 31;
        if (lane == 0)
            atomicAdd(&normsq[(b * 2 + t) * C0 + c], s);
    }
}

// ---------------- zero attn + normsq ---------------------------------------
__global__ void zero_small(float* __restrict__ attn, float* __restrict__ normsq)
{
    int i = blockIdx.x * 256 + threadIdx.x;
    if (i < BATCH * NH * HD * HD) attn[i] = 0.f;
    if (i < BATCH * 2 * C0) normsq[i] = 0.f;
}

// ---------------- tensor-core q·k^T (1-pass fp16) --------------------------
#define AT_NSPL 18
#define AT_KBLK (HW/AT_NSPL)   // 2048
#define AT_SK 128
#define AT_SUB (AT_KBLK/AT_SK) // 16
#define AT_SROW 136
#define AT_PLANE (48*AT_SROW*2)    // 13056
#define AT_STAGE (2*AT_PLANE)      // 26112
#define AT_SMEM (2*AT_STAGE)       // 52224

__global__ void __launch_bounds__(256) attn_mma(
    const fp16* __restrict__ q16, const fp16* __restrict__ k16,
    float* __restrict__ attn)
{
    extern __shared__ char smem[];
    const uint32_t sb = smem_u32(smem);
    const int tid  = threadIdx.x;
    const int wid  = tid >> 5;
    const int lane = tid & 31;

    const int bh = blockIdx.y;
    const int b = bh / NH, h = bh % NH;
    const size_t rowbase = ((size_t)b * C0 + h * HD) * HW;
    const fp16* pl[2] = { q16 + rowbase, k16 + rowbase };
    const size_t kblk0 = (size_t)blockIdx.x * AT_KBLK;

    float acc[3][6][4];
#pragma unroll
    for (int i = 0; i < 3; i++)
#pragma unroll
        for (int j = 0; j < 6; j++)
#pragma unroll
            for (int q = 0; q < 4; q++) acc[i][j][q] = 0.f;

    auto fill = [&](int sub, int stg) {
        uint32_t base = sb + stg * AT_STAGE;
        size_t k0 = kblk0 + (size_t)sub * AT_SK;
#pragma unroll
        for (int p = 0; p < 2; p++) {
#pragma unroll
            for (int r = 0; r < 3; r++) {
                int cc = tid + r * 256;
                int row = cc >> 4, seg = cc & 15;
                cpa16(base + p * AT_PLANE + (uint32_t)(row * AT_SROW + seg * 8) * 2,
                      pl[p] + (size_t)row * HW + k0 + seg * 8, 16);
            }
        }
        CP_COMMIT();
    };

    fill(0, 0);

    const int kofs = wid * 16;
    const int a_r = lane & 15;
    const int a_c = kofs + (lane >> 4) * 8;
    const int b_r = (lane & 7) + ((lane >> 4) & 1) * 8;
    const int b_c = kofs + ((lane >> 3) & 1) * 8;

    for (int sub = 0; sub < AT_SUB; sub++) {
        CP_WAIT(0);
        __syncthreads();
        if (sub < AT_SUB - 1) fill(sub + 1, (sub + 1) & 1);

        uint32_t base = sb + (sub & 1) * AT_STAGE;
        uint32_t qf[3][4], kf[3][4];
#pragma unroll
        for (int mt = 0; mt < 3; mt++) {
            uint32_t ao = (uint32_t)((mt * 16 + a_r) * AT_SROW + a_c) * 2;
            ldsm4(base + 0 * AT_PLANE + ao, qf[mt]);
        }
#pragma unroll
        for (int nt2 = 0; nt2 < 3; nt2++) {
            uint32_t bo = (uint32_t)((nt2 * 16 + b_r) * AT_SROW + b_c) * 2;
            ldsm4(base + 1 * AT_PLANE + bo, kf[nt2]);
        }
#pragma unroll
        for (int mt = 0; mt < 3; mt++)
#pragma unroll
            for (int nt = 0; nt < 6; nt++)
                mma16816(acc[mt][nt], qf[mt], &kf[nt >> 1][(nt & 1) * 2]);
        __syncthreads();
    }

    float* red = reinterpret_cast<float*>(smem);   // [48][49]
    for (int i = tid; i < 48 * 49; i += 256) red[i] = 0.f;
    __syncthreads();
    const int erow = lane >> 2;
    const int ecol = (lane & 3) * 2;
#pragma unroll
    for (int mt = 0; mt < 3; mt++) {
        int r0 = mt * 16 + erow;
#pragma unroll
        for (int nt = 0; nt < 6; nt++) {
            int cc = nt * 8 + ecol;
            atomicAdd(&red[r0 * 49 + cc],       acc[mt][nt][0]);
            atomicAdd(&red[r0 * 49 + cc + 1],   acc[mt][nt][1]);
            atomicAdd(&red[(r0 + 8) * 49 + cc],     acc[mt][nt][2]);
            atomicAdd(&red[(r0 + 8) * 49 + cc + 1], acc[mt][nt][3]);
        }
    }
    __syncthreads();
    float* ap = attn + (size_t)bh * HD * HD;
    for (int i = tid; i < HD * HD; i += 256) {
        int r = i / HD, cl = i % HD;
        atomicAdd(&ap[i], red[r * 49 + cl]);
    }
}

// ---------------- scale by norms + temperature, softmax over e -------------
__global__ void softmax_attn(float* __restrict__ attn, const float* __restrict__ normsq,
                             const float* __restrict__ logtemp)
{
    const int bh = blockIdx.x;
    const int b = bh / NH, h = bh % NH;
    const int d = threadIdx.x;
    if (d >= HD) return;

    float lt = logtemp[h];
    float temp = (lt > 20.f ? lt : log1pf(expf(lt))) + 1e-6f;

    const float* nq = normsq + (b * 2 + 0) * C0 + h * HD;
    const float* nk = normsq + (b * 2 + 1) * C0 + h * HD;
    float* row = attn + ((size_t)bh * HD + d) * HD;
    const float qn = fmaxf(sqrtf(nq[d]), 1e-12f);

    float vals[HD];
    float mx = -1e30f;
#pragma unroll
    for (int e = 0; e < HD; e++) {
        float kn = fmaxf(sqrtf(nk[e]), 1e-12f);
        float v = row[e] / (qn * kn) * temp;
        vals[e] = v;
        mx = fmaxf(mx, v);
    }
    float s = 0.f;
#pragma unroll
    for (int e = 0; e < HD; e++) {
        vals[e] = expf(vals[e] - mx);
        s += vals[e];
    }
    float inv = 1.f / s;
#pragma unroll
    for (int e = 0; e < HD; e++) row[e] = vals[e] * inv;
}

// ---------------- W2[b] = w_proj @ blockdiag(attn[b]) -> fp16 --------------
__global__ void build_w2(const float* __restrict__ wproj, const float* __restrict__ attn,
                         fp16* __restrict__ w2)
{
    int idx = blockIdx.x * 256 + threadIdx.x;
    if (idx >= BATCH * C0 * C0) return;
    int cc = idx % C0;
    int o  = (idx / C0) % C0;
    int b  = idx / (C0 * C0);
    int h = cc / HD, e = cc % HD;
    float s = 0.f;
#pragma unroll
    for (int d = 0; d < HD; d++)
        s += wproj[o * C0 + h * HD + d] * attn[(((size_t)b * NH + h) * HD + d) * HD + e];
    w2[idx] = __float2half_rn(s);
}

// ---------------- launcher -------------------------------------------------
extern "C" void kernel_launch(void* const* d_in, const int* in_sizes, int n_in,
                              void* d_out, int out_size)
{
    const float* x      = (const float*)d_in[0];
    const float* w_qkv  = (const float*)d_in[1];
    const float* w_dw   = (const float*)d_in[2];
    const float* w_proj = (const float*)d_in[3];
    const float* ltemp  = (const float*)d_in[4];
    float* out = (float*)d_out;

    float *normsq, *attn;
    fp16 *qkv1, *x16, *v16, *k16, *q16, *wq16, *w216;
    cudaGetSymbolAddress((void**)&qkv1, g_qkv1);
    cudaGetSymbolAddress((void**)&normsq, g_normsq);
    cudaGetSymbolAddress((void**)&attn, g_attn);
    cudaGetSymbolAddress((void**)&x16, g_x16);
    cudaGetSymbolAddress((void**)&v16, g_v16);
    cudaGetSymbolAddress((void**)&k16, g_k16);
    cudaGetSymbolAddress((void**)&q16, g_q16);
    cudaGetSymbolAddress((void**)&wq16, g_wq16);
    cudaGetSymbolAddress((void**)&w216, g_w216);

    cudaFuncSetAttribute(gemm_mma<true>,  cudaFuncAttributeMaxDynamicSharedMemorySize, SMEM_B);
    cudaFuncSetAttribute(gemm_mma<false>, cudaFuncAttributeMaxDynamicSharedMemorySize, SMEM_B);
    cudaFuncSetAttribute(attn_mma, cudaFuncAttributeMaxDynamicSharedMemorySize, AT_SMEM);

    // 0) convert x, w_qkv -> fp16; zero accumulators
    {
        int total = BATCH * C0 * HW;
        cvt_f16<<<total / 8 / 256, 256>>>(x, x16, total);
        int wtot = C3 * C0;
        cvt_f16<<<(wtot / 8 + 255) / 256, 256>>>(w_qkv, wq16, wtot);
        zero_small<<<(BATCH * NH * HD * HD + 255) / 256, 256>>>(attn, normsq);
    }
    // 1) qkv1 = w_qkv @ x  (1-pass, fp16 out)  M=576 -> 9 tiles of 64
    {
        dim3 grid(HW / BN, C3 / BM, BATCH);
        gemm_mma<true><<<grid, 128, SMEM_B>>>(wq16, x16, qkv1,
                                              HW, 0, (size_t)C0 * HW,
                                              (size_t)C3 * HW);
    }
    // 2) fused depthwise 3x3 -> q,k,v fp16 + normsq
    {
        dim3 grid(HH / DW_TY, BATCH * C3);
        dwconv_fused<<<grid, dim3(DW_TX, DW_TY)>>>(qkv1, w_dw, q16, k16, v16, normsq);
    }
    // 3) tensor-core q.k^T (1-pass)
    {
        dim3 grid(AT_NSPL, BATCH * NH);
        attn_mma<<<grid, 256, AT_SMEM>>>(q16, k16, attn);
    }
    // 4) softmax
    softmax_attn<<<BATCH * NH, 64>>>(attn, normsq, ltemp);
    // 5) W2 -> fp16
    build_w2<<<(BATCH * C0 * C0 + 255) / 256, 256>>>(w_proj, attn, w216);
    // 6) out = W2 @ v  (1-pass, fp32 out)  M=192 -> 3 tiles of 64
    {
        dim3 grid(HW / BN, C0 / BM, BATCH);
        gemm_mma<false><<<grid, 128, SMEM_B>>>(w216, v16, out,
                                               HW, (size_t)C0 * C0,
                                               (size_t)C0 * HW, (size_t)C0 * HW);
    }
}